// round 15
// baseline (speedup 1.0000x reference)
#include <cuda_runtime.h>
#include <cuda_bf16.h>
#include <cstdint>

#define VJ 25
#define NBATCH 64
typedef __nv_bfloat16 bf16;

// ---------------- static device scratch ----------------
__device__ bf16  g_Xh[30720000], g_Xl[30720000];     // tconv split-bf16 outputs [n][m][C]
__device__ bf16  g_Gh[61440000], g_Gl[61440000];     // mix(+adj) out, split bf16
__device__ bf16  g_WSh[262144],  g_WSl[262144];      // split 1x1 weights [c][o]
__device__ bf16  g_WTh[2359296], g_WTl[2359296];     // split temporal weights [tap][i][o]

// ---------------- helpers ----------------
__device__ __forceinline__ uint32_t sptr(const void* p) {
    return (uint32_t)__cvta_generic_to_shared(p);
}
__device__ __forceinline__ void split2(float v, bf16& h, bf16& l) {
    h = __float2bfloat16(v);
    l = __float2bfloat16(v - __bfloat162float(h));
}
__device__ __forceinline__ float2 ffma2(float2 d, float2 a, float2 b) {
    unsigned long long ud = reinterpret_cast<unsigned long long&>(d);
    unsigned long long ua = reinterpret_cast<unsigned long long&>(a);
    unsigned long long ub = reinterpret_cast<unsigned long long&>(b);
    asm("fma.rn.f32x2 %0, %1, %2, %0;" : "+l"(ud) : "l"(ua), "l"(ub));
    return reinterpret_cast<float2&>(ud);
}
__device__ __forceinline__ void ldsm_x4(uint32_t* r, uint32_t addr) {
    asm volatile("ldmatrix.sync.aligned.m8n8.x4.shared.b16 {%0,%1,%2,%3}, [%4];"
                 : "=r"(r[0]), "=r"(r[1]), "=r"(r[2]), "=r"(r[3]) : "r"(addr));
}
__device__ __forceinline__ void ldsm_x4_t(uint32_t* r, uint32_t addr) {
    asm volatile("ldmatrix.sync.aligned.m8n8.x4.trans.shared.b16 {%0,%1,%2,%3}, [%4];"
                 : "=r"(r[0]), "=r"(r[1]), "=r"(r[2]), "=r"(r[3]) : "r"(addr));
}
__device__ __forceinline__ void mma16816(float* d, const uint32_t* a, const uint32_t* b) {
    asm volatile(
        "mma.sync.aligned.m16n8k16.row.col.f32.bf16.bf16.f32 "
        "{%0,%1,%2,%3}, {%4,%5,%6,%7}, {%8,%9}, {%0,%1,%2,%3};"
        : "+f"(d[0]), "+f"(d[1]), "+f"(d[2]), "+f"(d[3])
        : "r"(a[0]), "r"(a[1]), "r"(a[2]), "r"(a[3]), "r"(b[0]), "r"(b[1]));
}
__device__ __forceinline__ void cpasync16(uint32_t d, const void* g, int ok) {
    asm volatile("cp.async.cg.shared.global [%0], [%1], 16, %2;"
                 :: "r"(d), "l"(g), "r"(ok ? 16 : 0) : "memory");
}

// ---------------- fused weight split ----------------
__global__ void split_both(const float* __restrict__ ws, const float* __restrict__ wt,
                           bf16* __restrict__ wsh, bf16* __restrict__ wsl,
                           bf16* __restrict__ wth, bf16* __restrict__ wtl,
                           int Cout, int Cin, int Kp) {
    int idx = blockIdx.x * 256 + threadIdx.x;
    int nws = Kp * Cout;
    if (idx < nws) {
        int c = idx / Cout, o = idx - c * Cout;
        float v = (c < Cin) ? ws[o * Cin + c] : 0.f;
        bf16 hh, ll; split2(v, hh, ll);
        wsh[idx] = hh; wsl[idx] = ll;
        return;
    }
    int j = idx - nws;
    if (j < 9 * Cout * Cout) {
        int k = j / (Cout * Cout);
        int r = j - k * Cout * Cout;
        int i = r / Cout, o = r - i * Cout;
        float v = wt[((size_t)o * Cout + i) * 9 + k];
        bf16 hh, ll; split2(v, hh, ll);
        wth[j] = hh; wtl[j] = ll;   // [(tap*C + i)*C + o]
    }
}

// ---------------- adjacency, scalar (layer 0 only: C=3 -> Kp=32) ----------------
__global__ void adj_kernel(const float* __restrict__ in, bf16* __restrict__ Hh,
                           bf16* __restrict__ Hl, const float* __restrict__ A,
                           int C, int Kp) {
    __shared__ float sA[VJ * VJ];
    __shared__ float sF[VJ * 256];
    const size_t bin = (size_t)blockIdx.x * VJ * C;
    const size_t bout = (size_t)blockIdx.x * VJ * Kp;
    for (int i = threadIdx.x; i < VJ * VJ; i += 256) sA[i] = A[i];
    const int tot = VJ * C;
    for (int i = threadIdx.x; i < tot; i += 256) sF[i] = in[bin + i];
    __syncthreads();
    const int outn = VJ * Kp;
    for (int i = threadIdx.x; i < outn; i += 256) {
        int w = i / Kp, c = i - w * Kp;
        float acc = 0.f;
        if (c < C) {
            #pragma unroll
            for (int v = 0; v < VJ; v++) acc = fmaf(sA[v * VJ + w], sF[v * C + c], acc);
        }
        bf16 hh, ll; split2(acc, hh, ll);
        Hh[bout + i] = hh; Hl[bout + i] = ll;
    }
}

// ---------------- stride-1 tconv: 64x64 warp tiles, templated thread count ----------
// MODE_OUT: 1 = relu + split-bf16 [n][m][C]; 2 = relu fp32 NCHW (final layer).
template <int BM, int BN, int MODE_OUT>
__global__ void __launch_bounds__((BM / 64) * (BN / 64) * 32,
                                  256 / ((BM / 64) * (BN / 64) * 32)) tconv_w64(
    const bf16* __restrict__ Ah, const bf16* __restrict__ Al,
    const bf16* __restrict__ Bh, const bf16* __restrict__ Bl,
    float* __restrict__ OutF, bf16* __restrict__ OutH, bf16* __restrict__ OutL,
    int M, int C, int Tout) {

    constexpr int NT = (BM / 64) * (BN / 64) * 32;
    constexpr int WR = BM + 200;
    constexpr int APITCH = 24;
    constexpr int A_ST = WR * APITCH;
    constexpr int BPITCH = BN + 8;
    constexpr int B_ST = 16 * BPITCH;
    constexpr int WM = BM / 64;
    constexpr int BSEG = BN / 8;
    extern __shared__ __align__(128) bf16 smem[];
    bf16* aH = smem;
    bf16* aL = smem + A_ST;
    bf16* bB = smem + 2 * A_ST;

    const int tid = threadIdx.x;
    const int lane = tid & 31, wid = tid >> 5;
    const int wm = wid % WM, wn = wid / WM;
    const int m0 = blockIdx.x * BM;
    const int n0 = blockIdx.y * BN;
    const int bz = blockIdx.z;

    const bf16* An_h = Ah + (size_t)bz * M * C;
    const bf16* An_l = Al + (size_t)bz * M * C;

    float acc[4][8][4];
    #pragma unroll
    for (int a = 0; a < 4; a++)
        #pragma unroll
        for (int b = 0; b < 8; b++)
            #pragma unroll
            for (int c = 0; c < 4; c++) acc[a][b][c] = 0.f;

    const int nch = C >> 4;
    for (int ch = 0; ch < nch; ch++) {
        const int c0 = ch << 4;
        for (int idx = tid; idx < WR * 2; idx += NT) {
            int w = idx >> 1, seg = idx & 1;
            int flat = m0 - 100 + w;
            int ok = (flat >= 0 && flat < M);
            size_t g = ok ? ((size_t)flat * C + c0 + seg * 8) : 0;
            uint32_t d = sptr(aH + w * APITCH + seg * 8);
            cpasync16(d, An_h + g, ok);
            cpasync16(d + (uint32_t)(A_ST * 2), An_l + g, ok);
        }
        for (int idx = tid; idx < 9 * 16 * BSEG; idx += NT) {
            int tap = idx / (16 * BSEG);
            int r = idx - tap * 16 * BSEG;
            int row = r / BSEG, seg = r - row * BSEG;
            size_t o = ((size_t)(tap * C + c0 + row)) * C + n0 + seg * 8;
            uint32_t d = sptr(bB + tap * 2 * B_ST + row * BPITCH + seg * 8);
            cpasync16(d, Bh + o, 1);
            cpasync16(d + (uint32_t)(B_ST * 2), Bl + o, 1);
        }
        asm volatile("cp.async.commit_group;" ::: "memory");
        asm volatile("cp.async.wait_group 0;" ::: "memory");
        __syncthreads();

        for (int tap = 0; tap < 9; tap++) {
            const bf16* bH = bB + tap * 2 * B_ST;
            const bf16* bL = bH + B_ST;
            const int woff = 25 * tap;
            uint32_t ah[4][4], al[4][4], bh[8][2], bl[8][2];
            #pragma unroll
            for (int mt = 0; mt < 4; mt++) {
                int row = woff + wm * 64 + mt * 16 + (lane & 15);
                int col = (lane >> 4) * 8;
                ldsm_x4(ah[mt], sptr(aH + row * APITCH + col));
                ldsm_x4(al[mt], sptr(aL + row * APITCH + col));
            }
            #pragma unroll
            for (int np = 0; np < 4; np++) {
                uint32_t t0[4], t1[4];
                int krow = lane & 15;
                int col = wn * 64 + np * 16 + (lane >> 4) * 8;
                ldsm_x4_t(t0, sptr(bH + krow * BPITCH + col));
                ldsm_x4_t(t1, sptr(bL + krow * BPITCH + col));
                bh[np * 2][0] = t0[0]; bh[np * 2][1] = t0[1];
                bh[np * 2 + 1][0] = t0[2]; bh[np * 2 + 1][1] = t0[3];
                bl[np * 2][0] = t1[0]; bl[np * 2][1] = t1[1];
                bl[np * 2 + 1][0] = t1[2]; bl[np * 2 + 1][1] = t1[3];
            }
            #pragma unroll
            for (int mt = 0; mt < 4; mt++)
                #pragma unroll
                for (int nt = 0; nt < 8; nt++) {
                    mma16816(acc[mt][nt], ah[mt], bh[nt]);
                    mma16816(acc[mt][nt], ah[mt], bl[nt]);
                    mma16816(acc[mt][nt], al[mt], bh[nt]);
                }
        }
        __syncthreads();
    }

    const int rbase = m0 + wm * 64 + (lane >> 2);
    const int cbase = n0 + wn * 64 + 2 * (lane & 3);
    #pragma unroll
    for (int mt = 0; mt < 4; mt++) {
        #pragma unroll
        for (int half = 0; half < 2; half++) {
            int row = rbase + mt * 16 + half * 8;
            if (row >= M) continue;
            #pragma unroll
            for (int nt = 0; nt < 8; nt++) {
                int col = cbase + nt * 8;
                float x = fmaxf(acc[mt][nt][half * 2 + 0], 0.f);
                float y = fmaxf(acc[mt][nt][half * 2 + 1], 0.f);
                if (MODE_OUT == 1) {
                    bf16 hx, lx, hy, ly;
                    split2(x, hx, lx); split2(y, hy, ly);
                    __nv_bfloat162 ph; ph.x = hx; ph.y = hy;
                    __nv_bfloat162 pl2; pl2.x = lx; pl2.y = ly;
                    size_t o = ((size_t)bz * M + row) * C + col;
                    *(__nv_bfloat162*)(OutH + o) = ph;
                    *(__nv_bfloat162*)(OutL + o) = pl2;
                } else {
                    int t = row / VJ, v = row - t * VJ;
                    OutF[(((size_t)bz * C + col) * Tout + t) * VJ + v] = x;
                    OutF[(((size_t)bz * C + col + 1) * Tout + t) * VJ + v] = y;
                }
            }
        }
    }
}

// ---------------- stride-2 tconv (PROVEN core); split-bf16 out ----------------
__global__ void __launch_bounds__(128, 2) tconv_s2w(
    const bf16* __restrict__ Ah, const bf16* __restrict__ Al,
    const bf16* __restrict__ Bh, const bf16* __restrict__ Bl,
    bf16* __restrict__ OutH, bf16* __restrict__ OutL, int Mout, int C, int Tin) {

    constexpr int BM = 250, BN = 64;
    constexpr int WR = 675;
    constexpr int APITCH = 24;
    constexpr int A_ST = WR * APITCH;
    constexpr int BPITCH = BN + 8;
    constexpr int B_ST = 16 * BPITCH;
    constexpr int BSEG = BN / 8;
    extern __shared__ __align__(128) bf16 smem[];
    bf16* aH = smem;
    bf16* aL = smem + A_ST;
    bf16* bB = smem + 2 * A_ST;
    __shared__ int rowmap[256];

    const int tid = threadIdx.x;
    const int lane = tid & 31, wid = tid >> 5;
    const int wm = wid;
    const int m0 = blockIdx.x * BM;
    const int n0 = blockIdx.y * BN;
    const int bz = blockIdx.z;
    const int Min = Tin * VJ;
    const int t0 = m0 / VJ;
    const int f0 = 2 * m0 - 100;

    for (int r = tid; r < 256; r += 128) {
        int gm = m0 + r;
        int rmv = 0;
        if (r < BM && gm < Mout) {
            int t = gm / VJ, v = gm - t * VJ;
            rmv = 50 * (t - t0) + v;
        }
        rowmap[r] = rmv;
    }
    const bf16* An_h = Ah + (size_t)bz * Min * C;
    const bf16* An_l = Al + (size_t)bz * Min * C;
    __syncthreads();

    int rm[4];
    #pragma unroll
    for (int mt = 0; mt < 4; mt++)
        rm[mt] = rowmap[wm * 64 + mt * 16 + (lane & 15)];

    float acc[4][8][4];
    #pragma unroll
    for (int a = 0; a < 4; a++)
        #pragma unroll
        for (int b = 0; b < 8; b++)
            #pragma unroll
            for (int c = 0; c < 4; c++) acc[a][b][c] = 0.f;

    const int nch = C >> 4;
    for (int ch = 0; ch < nch; ch++) {
        const int c0 = ch << 4;
        for (int idx = tid; idx < WR * 2; idx += 128) {
            int w = idx >> 1, seg = idx & 1;
            int flat = f0 + w;
            int ok = (flat >= 0 && flat < Min);
            size_t g = ok ? ((size_t)flat * C + c0 + seg * 8) : 0;
            uint32_t d = sptr(aH + w * APITCH + seg * 8);
            cpasync16(d, An_h + g, ok);
            cpasync16(d + (uint32_t)(A_ST * 2), An_l + g, ok);
        }
        for (int idx = tid; idx < 9 * 16 * BSEG; idx += 128) {
            int tap = idx / (16 * BSEG);
            int r = idx - tap * 16 * BSEG;
            int row = r / BSEG, seg = r - row * BSEG;
            size_t o = ((size_t)(tap * C + c0 + row)) * C + n0 + seg * 8;
            uint32_t d = sptr(bB + tap * 2 * B_ST + row * BPITCH + seg * 8);
            cpasync16(d, Bh + o, 1);
            cpasync16(d + (uint32_t)(B_ST * 2), Bl + o, 1);
        }
        asm volatile("cp.async.commit_group;" ::: "memory");
        asm volatile("cp.async.wait_group 0;" ::: "memory");
        __syncthreads();

        for (int tap = 0; tap < 9; tap++) {
            const bf16* bH = bB + tap * 2 * B_ST;
            const bf16* bL = bH + B_ST;
            const int woff = 25 * tap;
            uint32_t ah[4][4], al[4][4], bh[8][2], bl[8][2];
            #pragma unroll
            for (int mt = 0; mt < 4; mt++) {
                int row = rm[mt] + woff;
                int col = (lane >> 4) * 8;
                ldsm_x4(ah[mt], sptr(aH + row * APITCH + col));
                ldsm_x4(al[mt], sptr(aL + row * APITCH + col));
            }
            #pragma unroll
            for (int np = 0; np < 4; np++) {
                uint32_t t0r[4], t1r[4];
                int krow = lane & 15;
                int col = np * 16 + (lane >> 4) * 8;
                ldsm_x4_t(t0r, sptr(bH + krow * BPITCH + col));
                ldsm_x4_t(t1r, sptr(bL + krow * BPITCH + col));
                bh[np * 2][0] = t0r[0]; bh[np * 2][1] = t0r[1];
                bh[np * 2 + 1][0] = t0r[2]; bh[np * 2 + 1][1] = t0r[3];
                bl[np * 2][0] = t1r[0]; bl[np * 2][1] = t1r[1];
                bl[np * 2 + 1][0] = t1r[2]; bl[np * 2 + 1][1] = t1r[3];
            }
            #pragma unroll
            for (int mt = 0; mt < 4; mt++)
                #pragma unroll
                for (int nt = 0; nt < 8; nt++) {
                    mma16816(acc[mt][nt], ah[mt], bh[nt]);
                    mma16816(acc[mt][nt], ah[mt], bl[nt]);
                    mma16816(acc[mt][nt], al[mt], bh[nt]);
                }
        }
        __syncthreads();
    }

    const int rbase = wm * 64 + (lane >> 2);
    const int cbase = n0 + 2 * (lane & 3);
    #pragma unroll
    for (int mt = 0; mt < 4; mt++) {
        #pragma unroll
        for (int half = 0; half < 2; half++) {
            int lr = rbase + mt * 16 + half * 8;
            int row = m0 + lr;
            if (lr >= BM || row >= Mout) continue;
            #pragma unroll
            for (int nt = 0; nt < 8; nt++) {
                int col = cbase + nt * 8;
                float x = fmaxf(acc[mt][nt][half * 2 + 0], 0.f);
                float y = fmaxf(acc[mt][nt][half * 2 + 1], 0.f);
                bf16 hx, lx, hy, ly;
                split2(x, hx, lx); split2(y, hy, ly);
                __nv_bfloat162 ph; ph.x = hx; ph.y = hy;
                __nv_bfloat162 pl2; pl2.x = lx; pl2.y = ly;
                size_t o = ((size_t)bz * Mout + row) * C + col;
                *(__nv_bfloat162*)(OutH + o) = ph;
                *(__nv_bfloat162*)(OutL + o) = pl2;
            }
        }
    }
}

// ---------------- layer-0 mix GEMM (PROVEN) ----------------
__global__ void __launch_bounds__(128, 2) gemm64L0(
    const bf16* __restrict__ Ah, const bf16* __restrict__ Al,
    const bf16* __restrict__ Bh, const bf16* __restrict__ Bl,
    bf16* __restrict__ OutH, bf16* __restrict__ OutL,
    int M, int Ka, int N) {

    constexpr int BM = 256, BN = 64;
    constexpr int STAGES = 3;
    constexpr int APITCH = 24;
    constexpr int A_ST = BM * APITCH;
    constexpr int BPITCH = BN + 8;
    constexpr int B_ST = 16 * BPITCH;
    constexpr int STG = 2 * A_ST + 2 * B_ST;
    constexpr int BSEG = BN / 8;
    extern __shared__ __align__(128) bf16 smem[];

    const int tid = threadIdx.x;
    const int lane = tid & 31, wid = tid >> 5;
    const int wm = wid;
    const int m0 = blockIdx.x * BM;
    const int n0 = blockIdx.y * BN;

    float acc[4][8][4];
    #pragma unroll
    for (int a = 0; a < 4; a++)
        #pragma unroll
        for (int b = 0; b < 8; b++)
            #pragma unroll
            for (int c = 0; c < 4; c++) acc[a][b][c] = 0.f;

    const int nch = Ka >> 4;
    auto load_stage = [&](int s, int ch) {
        int c0 = ch << 4;
        bf16* aH = smem + s * STG;
        bf16* bB = aH + 2 * A_ST;
        for (int idx = tid; idx < BM * 2; idx += 128) {
            int w = idx >> 1, seg = idx & 1;
            int gm = m0 + w;
            int ok = gm < M;
            size_t g = ok ? ((size_t)gm * Ka + c0 + seg * 8) : 0;
            uint32_t d = sptr(aH + w * APITCH + seg * 8);
            cpasync16(d, Ah + g, ok);
            cpasync16(d + (uint32_t)(A_ST * 2), Al + g, ok);
        }
        for (int idx = tid; idx < 16 * BSEG; idx += 128) {
            int row = idx / BSEG, seg = idx - row * BSEG;
            size_t o = ((size_t)(c0 + row)) * N + n0 + seg * 8;
            uint32_t d = sptr(bB + row * BPITCH + seg * 8);
            cpasync16(d, Bh + o, 1);
            cpasync16(d + (uint32_t)(B_ST * 2), Bl + o, 1);
        }
    };

    #pragma unroll
    for (int s = 0; s < STAGES - 1; s++) {
        if (s < nch) load_stage(s, s);
        asm volatile("cp.async.commit_group;" ::: "memory");
    }
    for (int ch = 0; ch < nch; ch++) {
        asm volatile("cp.async.wait_group %0;" :: "n"(STAGES - 2) : "memory");
        __syncthreads();
        int pf = ch + STAGES - 1;
        if (pf < nch) load_stage(pf % STAGES, pf);
        asm volatile("cp.async.commit_group;" ::: "memory");

        const int s = ch % STAGES;
        const bf16* aH = smem + s * STG;
        const bf16* aL = aH + A_ST;
        const bf16* bH = aH + 2 * A_ST;
        const bf16* bL = bH + B_ST;
        uint32_t ah[4][4], al[4][4], bh[8][2], bl[8][2];
        #pragma unroll
        for (int mt = 0; mt < 4; mt++) {
            int row = wm * 64 + mt * 16 + (lane & 15);
            int col = (lane >> 4) * 8;
            ldsm_x4(ah[mt], sptr(aH + row * APITCH + col));
            ldsm_x4(al[mt], sptr(aL + row * APITCH + col));
        }
        #pragma unroll
        for (int np = 0; np < 4; np++) {
            uint32_t t0[4], t1[4];
            int krow = lane & 15;
            int col = np * 16 + (lane >> 4) * 8;
            ldsm_x4_t(t0, sptr(bH + krow * BPITCH + col));
            ldsm_x4_t(t1, sptr(bL + krow * BPITCH + col));
            bh[np * 2][0] = t0[0]; bh[np * 2][1] = t0[1];
            bh[np * 2 + 1][0] = t0[2]; bh[np * 2 + 1][1] = t0[3];
            bl[np * 2][0] = t1[0]; bl[np * 2][1] = t1[1];
            bl[np * 2 + 1][0] = t1[2]; bl[np * 2 + 1][1] = t1[3];
        }
        #pragma unroll
        for (int mt = 0; mt < 4; mt++)
            #pragma unroll
            for (int nt = 0; nt < 8; nt++) {
                mma16816(acc[mt][nt], ah[mt], bh[nt]);
                mma16816(acc[mt][nt], ah[mt], bl[nt]);
                mma16816(acc[mt][nt], al[mt], bh[nt]);
            }
    }

    const int rbase = m0 + wm * 64 + (lane >> 2);
    const int cbase = n0 + 2 * (lane & 3);
    #pragma unroll
    for (int mt = 0; mt < 4; mt++) {
        #pragma unroll
        for (int half = 0; half < 2; half++) {
            int row = rbase + mt * 16 + half * 8;
            if (row >= M) continue;
            #pragma unroll
            for (int nt = 0; nt < 8; nt++) {
                int col = cbase + nt * 8;
                float x = fmaxf(acc[mt][nt][half * 2 + 0], 0.f);
                float y = fmaxf(acc[mt][nt][half * 2 + 1], 0.f);
                bf16 hx, lx, hy, ly;
                split2(x, hx, lx); split2(y, hy, ly);
                __nv_bfloat162 ph; ph.x = hx; ph.y = hy;
                __nv_bfloat162 pl2; pl2.x = lx; pl2.y = ly;
                *(__nv_bfloat162*)(OutH + (size_t)row * N + col) = ph;
                *(__nv_bfloat162*)(OutL + (size_t)row * N + col) = pl2;
            }
        }
    }
}

// ---------------- fused mix + adjacency (layers 1-9) ----------------
// Epilogue v2: register accumulators + ffma2 — each thread owns (t, col-pair),
// reads each P row once; all adjacency math in packed f32x2.
__global__ void __launch_bounds__(128, 2) mixadj(
    const bf16* __restrict__ Ah, const bf16* __restrict__ Al,
    const bf16* __restrict__ Bh, const bf16* __restrict__ Bl,
    const float* __restrict__ Aadj,
    bf16* __restrict__ OutH, bf16* __restrict__ OutL,
    int Mb, int Ka, int N) {

    constexpr int BM = 250, BMF = 256;
    constexpr int BN = 64;
    constexpr int STAGES = 3;
    constexpr int APITCH = 24;
    constexpr int A_ST = BMF * APITCH;
    constexpr int BPITCH = BN + 8;
    constexpr int B_ST = 16 * BPITCH;
    constexpr int STG = 2 * A_ST + 2 * B_ST;
    constexpr int BSEG = BN / 8;
    constexpr int PPITCH = 72;
    extern __shared__ __align__(128) bf16 smem[];
    __shared__ float sAdj[VJ * VJ];

    const int tid = threadIdx.x;
    const int lane = tid & 31, wid = tid >> 5;
    const int wm = wid;
    const int m0 = blockIdx.x * BM;
    const int n0 = blockIdx.y * BN;
    const int bz = blockIdx.z;

    for (int i = tid; i < VJ * VJ; i += 128) sAdj[i] = Aadj[i];

    const bf16* An_h = Ah + (size_t)bz * Mb * Ka;
    const bf16* An_l = Al + (size_t)bz * Mb * Ka;

    float acc[4][8][4];
    #pragma unroll
    for (int a = 0; a < 4; a++)
        #pragma unroll
        for (int b = 0; b < 8; b++)
            #pragma unroll
            for (int c = 0; c < 4; c++) acc[a][b][c] = 0.f;

    const int nch = Ka >> 4;
    auto load_stage = [&](int s, int ch) {
        int c0 = ch << 4;
        bf16* aH = smem + s * STG;
        bf16* bB = aH + 2 * A_ST;
        for (int idx = tid; idx < BMF * 2; idx += 128) {
            int w = idx >> 1, seg = idx & 1;
            int gm = m0 + w;
            int ok = gm < Mb;
            size_t g = ok ? ((size_t)gm * Ka + c0 + seg * 8) : 0;
            uint32_t d = sptr(aH + w * APITCH + seg * 8);
            cpasync16(d, An_h + g, ok);
            cpasync16(d + (uint32_t)(A_ST * 2), An_l + g, ok);
        }
        for (int idx = tid; idx < 16 * BSEG; idx += 128) {
            int row = idx / BSEG, seg = idx - row * BSEG;
            size_t o = ((size_t)(c0 + row)) * N + n0 + seg * 8;
            uint32_t d = sptr(bB + row * BPITCH + seg * 8);
            cpasync16(d, Bh + o, 1);
            cpasync16(d + (uint32_t)(B_ST * 2), Bl + o, 1);
        }
    };

    #pragma unroll
    for (int s = 0; s < STAGES - 1; s++) {
        if (s < nch) load_stage(s, s);
        asm volatile("cp.async.commit_group;" ::: "memory");
    }
    for (int ch = 0; ch < nch; ch++) {
        asm volatile("cp.async.wait_group %0;" :: "n"(STAGES - 2) : "memory");
        __syncthreads();
        int pf = ch + STAGES - 1;
        if (pf < nch) load_stage(pf % STAGES, pf);
        asm volatile("cp.async.commit_group;" ::: "memory");

        const int s = ch % STAGES;
        const bf16* aH = smem + s * STG;
        const bf16* aL = aH + A_ST;
        const bf16* bH = aH + 2 * A_ST;
        const bf16* bL = bH + B_ST;
        uint32_t ah[4][4], al[4][4], bh[8][2], bl[8][2];
        #pragma unroll
        for (int mt = 0; mt < 4; mt++) {
            int row = wm * 64 + mt * 16 + (lane & 15);
            int col = (lane >> 4) * 8;
            ldsm_x4(ah[mt], sptr(aH + row * APITCH + col));
            ldsm_x4(al[mt], sptr(aL + row * APITCH + col));
        }
        #pragma unroll
        for (int np = 0; np < 4; np++) {
            uint32_t t0[4], t1[4];
            int krow = lane & 15;
            int col = np * 16 + (lane >> 4) * 8;
            ldsm_x4_t(t0, sptr(bH + krow * BPITCH + col));
            ldsm_x4_t(t1, sptr(bL + krow * BPITCH + col));
            bh[np * 2][0] = t0[0]; bh[np * 2][1] = t0[1];
            bh[np * 2 + 1][0] = t0[2]; bh[np * 2 + 1][1] = t0[3];
            bl[np * 2][0] = t1[0]; bl[np * 2][1] = t1[1];
            bl[np * 2 + 1][0] = t1[2]; bl[np * 2 + 1][1] = t1[3];
        }
        #pragma unroll
        for (int mt = 0; mt < 4; mt++)
            #pragma unroll
            for (int nt = 0; nt < 8; nt++) {
                mma16816(acc[mt][nt], ah[mt], bh[nt]);
                mma16816(acc[mt][nt], ah[mt], bl[nt]);
                mma16816(acc[mt][nt], al[mt], bh[nt]);
            }
    }

    // ---- drain pipeline, stage P fp32 in smem ----
    asm volatile("cp.async.wait_group 0;" ::: "memory");
    __syncthreads();
    float* Ps = (float*)smem;
    {
        const int rb = wm * 64 + (lane >> 2);
        const int cb = 2 * (lane & 3);
        #pragma unroll
        for (int mt = 0; mt < 4; mt++) {
            #pragma unroll
            for (int half = 0; half < 2; half++) {
                int lr = rb + mt * 16 + half * 8;
                if (lr >= BM) continue;
                #pragma unroll
                for (int nt = 0; nt < 8; nt++) {
                    int col = cb + nt * 8;
                    float2 p = make_float2(acc[mt][nt][half * 2 + 0],
                                           acc[mt][nt][half * 2 + 1]);
                    *(float2*)&Ps[lr * PPITCH + col] = p;
                }
            }
        }
    }
    __syncthreads();

    // ---- adjacency: register accumulators, ffma2, each P row read once ----
    // tasks: 10 t-groups x 32 col-pairs = 320
    for (int task = tid; task < (BM / VJ) * (BN / 2); task += 128) {
        int t = task >> 5, c2 = task & 31;
        float2 accw[VJ];
        #pragma unroll
        for (int w = 0; w < VJ; w++) accw[w] = make_float2(0.f, 0.f);
        #pragma unroll
        for (int v = 0; v < VJ; v++) {
            float2 p = *(float2*)&Ps[(t * VJ + v) * PPITCH + c2 * 2];
            const float* arow = &sAdj[v * VJ];
            #pragma unroll
            for (int w = 0; w < VJ; w++) {
                float a = arow[w];
                accw[w] = ffma2(accw[w], make_float2(a, a), p);
            }
        }
        #pragma unroll
        for (int w = 0; w < VJ; w++) {
            int gm = m0 + t * VJ + w;
            if (gm >= Mb) continue;
            float xx = fmaxf(accw[w].x, 0.f);
            float yy = fmaxf(accw[w].y, 0.f);
            bf16 hx, lx, hy, ly;
            split2(xx, hx, lx); split2(yy, hy, ly);
            __nv_bfloat162 ph; ph.x = hx; ph.y = hy;
            __nv_bfloat162 pl2; pl2.x = lx; pl2.y = ly;
            size_t o = ((size_t)bz * Mb + gm) * N + n0 + c2 * 2;
            *(__nv_bfloat162*)(OutH + o) = ph;
            *(__nv_bfloat162*)(OutL + o) = pl2;
        }
    }
}

// ---------------- host orchestration ----------------
static inline int cdiv(int a, int b) { return (a + b - 1) / b; }

extern "C" void kernel_launch(void* const* d_in, const int* in_sizes, int n_in,
                              void* d_out, int out_size) {
    (void)out_size;
    const float* x = (const float*)d_in[0];
    const float* A = (const float*)d_in[1];

    bool interleaved = (n_in >= 4 && in_sizes[3] == 64 * 64 * 9);
    const float* ws[10];
    const float* wt[10];
    for (int i = 0; i < 10; i++) {
        if (interleaved) {
            ws[i] = (const float*)d_in[2 + 2 * i];
            wt[i] = (const float*)d_in[3 + 2 * i];
        } else {
            ws[i] = (const float*)d_in[2 + i];
            wt[i] = (const float*)d_in[12 + i];
        }
    }

    bf16 *Xh, *Xl, *Gh, *Gl, *WSh, *WSl, *WTh, *WTl;
    cudaGetSymbolAddress((void**)&Xh, g_Xh);
    cudaGetSymbolAddress((void**)&Xl, g_Xl);
    cudaGetSymbolAddress((void**)&Gh, g_Gh);
    cudaGetSymbolAddress((void**)&Gl, g_Gl);
    cudaGetSymbolAddress((void**)&WSh, g_WSh);
    cudaGetSymbolAddress((void**)&WSl, g_WSl);
    cudaGetSymbolAddress((void**)&WTh, g_WTh);
    cudaGetSymbolAddress((void**)&WTl, g_WTl);

    const int Cin[10]  = {3, 64, 64, 64, 64, 128, 128, 128, 256, 256};
    const int Cout[10] = {64, 64, 64, 64, 128, 128, 128, 256, 256, 256};
    const int Tin[10]  = {300, 300, 300, 300, 300, 150, 150, 150, 75, 75};
    const int Tout[10] = {300, 300, 300, 300, 150, 150, 150, 75, 75, 75};
    const int S[10]    = {1, 1, 1, 1, 2, 1, 1, 2, 1, 1};
    const int Kp[10]   = {32, 64, 64, 64, 64, 128, 128, 128, 256, 256};

    int wsOff[10], wtOff[10];
    {
        int o = 0, o2 = 0;
        for (int i = 0; i < 10; i++) {
            wsOff[i] = o;  o  += Kp[i] * Cout[i];
            wtOff[i] = o2; o2 += 9 * Cout[i] * Cout[i];
        }
    }

    constexpr int SMEM_W64  = (2 * 456 * 24 + 18 * 16 * 72) * 2;              // 85248
    constexpr int SMEM_W256 = (2 * 456 * 24 + 18 * 16 * 136) * 2;             // 122112
    constexpr int SMEM_S2   = (2 * 675 * 24 + 18 * 16 * 72) * 2;              // 106272
    constexpr int SMEM_GMX  = 3 * (2 * 256 * 24 + 2 * 16 * 72) * 2;           // 87552
    cudaFuncSetAttribute(tconv_w64<256, 64, 1>, cudaFuncAttributeMaxDynamicSharedMemorySize, SMEM_W64);
    cudaFuncSetAttribute(tconv_w64<256, 128, 1>, cudaFuncAttributeMaxDynamicSharedMemorySize, SMEM_W256);
    cudaFuncSetAttribute(tconv_w64<256, 128, 2>, cudaFuncAttributeMaxDynamicSharedMemorySize, SMEM_W256);
    cudaFuncSetAttribute(tconv_s2w, cudaFuncAttributeMaxDynamicSharedMemorySize, SMEM_S2);
    cudaFuncSetAttribute(gemm64L0, cudaFuncAttributeMaxDynamicSharedMemorySize, SMEM_GMX);
    cudaFuncSetAttribute(mixadj, cudaFuncAttributeMaxDynamicSharedMemorySize, SMEM_GMX);

    auto do_split = [&](int i) {
        int tot = Kp[i] * Cout[i] + 9 * Cout[i] * Cout[i];
        split_both<<<cdiv(tot, 256), 256>>>(ws[i], wt[i],
                                            WSh + wsOff[i], WSl + wsOff[i],
                                            WTh + wtOff[i], WTl + wtOff[i],
                                            Cout[i], Cin[i], Kp[i]);
    };
    auto do_tconv = [&](int i) {
        const int Mout = Tout[i] * VJ;
        if (S[i] == 1) {
            if (Cout[i] >= 128) {
                dim3 grid(cdiv(Mout, 256), Cout[i] / 128, NBATCH);
                if (i == 9)
                    tconv_w64<256, 128, 2><<<grid, 256, SMEM_W256>>>(
                        Gh, Gl, WTh + wtOff[i], WTl + wtOff[i], (float*)d_out,
                        nullptr, nullptr, Mout, Cout[i], Tout[i]);
                else
                    tconv_w64<256, 128, 1><<<grid, 256, SMEM_W256>>>(
                        Gh, Gl, WTh + wtOff[i], WTl + wtOff[i], nullptr,
                        Xh, Xl, Mout, Cout[i], Tout[i]);
            } else {
                dim3 grid(cdiv(Mout, 256), 1, NBATCH);
                tconv_w64<256, 64, 1><<<grid, 128, SMEM_W64>>>(
                    Gh, Gl, WTh + wtOff[i], WTl + wtOff[i], nullptr,
                    Xh, Xl, Mout, Cout[i], Tout[i]);
            }
        } else {
            dim3 grid(cdiv(Mout, 250), Cout[i] / 64, NBATCH);
            tconv_s2w<<<grid, 128, SMEM_S2>>>(
                Gh, Gl, WTh + wtOff[i], WTl + wtOff[i],
                Xh, Xl, Mout, Cout[i], Tin[i]);
        }
    };

    // Layer 0: adj (fp32 x) -> mix GEMM -> tconv. Order keeps tconv at capture idx 3.
    do_split(0);
    {
        const int NT = NBATCH * Tin[0];
        adj_kernel<<<NT, 256>>>(x, Xh, Xl, A, Cin[0], Kp[0]);
        const int M = NT * VJ;
        dim3 grid(cdiv(M, 256), 1);
        gemm64L0<<<grid, 128, SMEM_GMX>>>(Xh, Xl, WSh + wsOff[0], WSl + wsOff[0],
                                          Gh, Gl, M, Kp[0], Cout[0]);
        do_tconv(0);
    }
    for (int i = 1; i < 10; i++) do_split(i);
    for (int i = 1; i < 10; i++) {
        const int Mb = Tin[i] * VJ;
        dim3 grid(cdiv(Mb, 250), Cout[i] / 64, NBATCH);
        mixadj<<<grid, 128, SMEM_GMX>>>(Xh, Xl, WSh + wsOff[i], WSl + wsOff[i],
                                        A, Gh, Gl, Mb, Kp[i], Cout[i]);
        do_tconv(i);
    }
}

// round 16
// speedup vs baseline: 1.1346x; 1.1346x over previous
#include <cuda_runtime.h>
#include <cuda_bf16.h>
#include <cstdint>

#define VJ 25
#define NBATCH 64
typedef __nv_bfloat16 bf16;

// ---------------- static device scratch ----------------
__device__ float g_X[30720000];                      // tconv fp32 outputs (n, m, C)
__device__ bf16  g_Hh[30720000], g_Hl[30720000];     // adjacency out, split bf16
__device__ bf16  g_Gh[61440000], g_Gl[61440000];     // mix out, split bf16
__device__ bf16  g_WSh[262144],  g_WSl[262144];      // split 1x1 weights [c][o]
__device__ bf16  g_WTh[2359296], g_WTl[2359296];     // split temporal weights [tap][i][o]

// ---------------- helpers ----------------
__device__ __forceinline__ uint32_t sptr(const void* p) {
    return (uint32_t)__cvta_generic_to_shared(p);
}
__device__ __forceinline__ void split2(float v, bf16& h, bf16& l) {
    h = __float2bfloat16(v);
    l = __float2bfloat16(v - __bfloat162float(h));
}
__device__ __forceinline__ float2 ffma2(float2 d, float2 a, float2 b) {
    unsigned long long ud = reinterpret_cast<unsigned long long&>(d);
    unsigned long long ua = reinterpret_cast<unsigned long long&>(a);
    unsigned long long ub = reinterpret_cast<unsigned long long&>(b);
    asm("fma.rn.f32x2 %0, %1, %2, %0;" : "+l"(ud) : "l"(ua), "l"(ub));
    return reinterpret_cast<float2&>(ud);
}
__device__ __forceinline__ void ldsm_x4(uint32_t* r, uint32_t addr) {
    asm volatile("ldmatrix.sync.aligned.m8n8.x4.shared.b16 {%0,%1,%2,%3}, [%4];"
                 : "=r"(r[0]), "=r"(r[1]), "=r"(r[2]), "=r"(r[3]) : "r"(addr));
}
__device__ __forceinline__ void ldsm_x4_t(uint32_t* r, uint32_t addr) {
    asm volatile("ldmatrix.sync.aligned.m8n8.x4.trans.shared.b16 {%0,%1,%2,%3}, [%4];"
                 : "=r"(r[0]), "=r"(r[1]), "=r"(r[2]), "=r"(r[3]) : "r"(addr));
}
__device__ __forceinline__ void mma16816(float* d, const uint32_t* a, const uint32_t* b) {
    asm volatile(
        "mma.sync.aligned.m16n8k16.row.col.f32.bf16.bf16.f32 "
        "{%0,%1,%2,%3}, {%4,%5,%6,%7}, {%8,%9}, {%0,%1,%2,%3};"
        : "+f"(d[0]), "+f"(d[1]), "+f"(d[2]), "+f"(d[3])
        : "r"(a[0]), "r"(a[1]), "r"(a[2]), "r"(a[3]), "r"(b[0]), "r"(b[1]));
}
__device__ __forceinline__ void cpasync16(uint32_t d, const void* g, int ok) {
    asm volatile("cp.async.cg.shared.global [%0], [%1], 16, %2;"
                 :: "r"(d), "l"(g), "r"(ok ? 16 : 0) : "memory");
}

// ---------------- fused weight split ----------------
__global__ void split_both(const float* __restrict__ ws, const float* __restrict__ wt,
                           bf16* __restrict__ wsh, bf16* __restrict__ wsl,
                           bf16* __restrict__ wth, bf16* __restrict__ wtl,
                           int Cout, int Cin, int Kp) {
    int idx = blockIdx.x * 256 + threadIdx.x;
    int nws = Kp * Cout;
    if (idx < nws) {
        int c = idx / Cout, o = idx - c * Cout;
        float v = (c < Cin) ? ws[o * Cin + c] : 0.f;
        bf16 hh, ll; split2(v, hh, ll);
        wsh[idx] = hh; wsl[idx] = ll;
        return;
    }
    int j = idx - nws;
    if (j < 9 * Cout * Cout) {
        int k = j / (Cout * Cout);
        int r = j - k * Cout * Cout;
        int i = r / Cout, o = r - i * Cout;
        float v = wt[((size_t)o * Cout + i) * 9 + k];
        bf16 hh, ll; split2(v, hh, ll);
        wth[j] = hh; wtl[j] = ll;   // [(tap*C + i)*C + o]
    }
}

// ---------------- adjacency, scalar (layer 0) ----------------
__global__ void adj_kernel(const float* __restrict__ in, bf16* __restrict__ Hh,
                           bf16* __restrict__ Hl, const float* __restrict__ A,
                           int C, int Kp) {
    __shared__ float sA[VJ * VJ];
    __shared__ float sF[VJ * 256];
    const size_t bin = (size_t)blockIdx.x * VJ * C;
    const size_t bout = (size_t)blockIdx.x * VJ * Kp;
    for (int i = threadIdx.x; i < VJ * VJ; i += 256) sA[i] = A[i];
    const int tot = VJ * C;
    for (int i = threadIdx.x; i < tot; i += 256) sF[i] = in[bin + i];
    __syncthreads();
    const int outn = VJ * Kp;
    for (int i = threadIdx.x; i < outn; i += 256) {
        int w = i / Kp, c = i - w * Kp;
        float acc = 0.f;
        if (c < C) {
            #pragma unroll
            for (int v = 0; v < VJ; v++) acc = fmaf(sA[v * VJ + w], sF[v * C + c], acc);
        }
        bf16 hh, ll; split2(acc, hh, ll);
        Hh[bout + i] = hh; Hl[bout + i] = ll;
    }
}

// ---------------- adjacency, float4 + packed ffma2 (layers 1-9) ----------------
__global__ void adj_kernel4(const float* __restrict__ in, bf16* __restrict__ Hh,
                            bf16* __restrict__ Hl, const float* __restrict__ A,
                            int C) {
    __shared__ float sA[VJ * VJ];
    __shared__ __align__(16) float sF[VJ * 256];
    const size_t base = (size_t)blockIdx.x * VJ * C;
    for (int i = threadIdx.x; i < VJ * VJ; i += 256) sA[i] = A[i];
    const int tot4 = VJ * C / 4;
    const float4* in4 = (const float4*)(in + base);
    float4* sF4 = (float4*)sF;
    for (int i = threadIdx.x; i < tot4; i += 256) sF4[i] = in4[i];
    __syncthreads();
    const int C4 = C >> 2;
    for (int i = threadIdx.x; i < VJ * C4; i += 256) {
        int w = i / C4, c4 = i - w * C4;
        float2 a0 = make_float2(0.f, 0.f), a1 = make_float2(0.f, 0.f);
        #pragma unroll
        for (int v = 0; v < VJ; v++) {
            float a = sA[v * VJ + w];
            float4 f = sF4[v * C4 + c4];
            float2 aa = make_float2(a, a);
            a0 = ffma2(a0, aa, make_float2(f.x, f.y));
            a1 = ffma2(a1, aa, make_float2(f.z, f.w));
        }
        bf16 h0, l0, h1, l1, h2, l2, h3, l3;
        split2(a0.x, h0, l0); split2(a0.y, h1, l1);
        split2(a1.x, h2, l2); split2(a1.y, h3, l3);
        size_t o = base + (size_t)w * C + c4 * 4;
        __nv_bfloat162 ph0; ph0.x = h0; ph0.y = h1;
        __nv_bfloat162 ph1; ph1.x = h2; ph1.y = h3;
        __nv_bfloat162 pl0; pl0.x = l0; pl0.y = l1;
        __nv_bfloat162 pl1; pl1.x = l2; pl1.y = l3;
        *(__nv_bfloat162*)(Hh + o) = ph0;
        *(__nv_bfloat162*)(Hh + o + 2) = ph1;
        *(__nv_bfloat162*)(Hl + o) = pl0;
        *(__nv_bfloat162*)(Hl + o + 2) = pl1;
    }
}

// ---------------- stride-1 tconv: 64x64 warp tiles (PROVEN R13) ----------
template <int BM, int BN, int MODE_OUT>
__global__ void __launch_bounds__(128, 2) tconv_w64(
    const bf16* __restrict__ Ah, const bf16* __restrict__ Al,
    const bf16* __restrict__ Bh, const bf16* __restrict__ Bl,
    float* __restrict__ OutF, int M, int C, int Tout) {

    constexpr int WR = BM + 200;
    constexpr int APITCH = 24;
    constexpr int A_ST = WR * APITCH;
    constexpr int BPITCH = BN + 8;
    constexpr int B_ST = 16 * BPITCH;
    constexpr int WM = BM / 64;
    constexpr int BSEG = BN / 8;
    extern __shared__ __align__(128) bf16 smem[];
    bf16* aH = smem;
    bf16* aL = smem + A_ST;
    bf16* bB = smem + 2 * A_ST;

    const int tid = threadIdx.x;
    const int lane = tid & 31, wid = tid >> 5;
    const int wm = wid % WM, wn = wid / WM;
    const int m0 = blockIdx.x * BM;
    const int n0 = blockIdx.y * BN;
    const int bz = blockIdx.z;

    const bf16* An_h = Ah + (size_t)bz * M * C;
    const bf16* An_l = Al + (size_t)bz * M * C;

    float acc[4][8][4];
    #pragma unroll
    for (int a = 0; a < 4; a++)
        #pragma unroll
        for (int b = 0; b < 8; b++)
            #pragma unroll
            for (int c = 0; c < 4; c++) acc[a][b][c] = 0.f;

    const int nch = C >> 4;
    for (int ch = 0; ch < nch; ch++) {
        const int c0 = ch << 4;
        for (int idx = tid; idx < WR * 2; idx += 128) {
            int w = idx >> 1, seg = idx & 1;
            int flat = m0 - 100 + w;
            int ok = (flat >= 0 && flat < M);
            size_t g = ok ? ((size_t)flat * C + c0 + seg * 8) : 0;
            uint32_t d = sptr(aH + w * APITCH + seg * 8);
            cpasync16(d, An_h + g, ok);
            cpasync16(d + (uint32_t)(A_ST * 2), An_l + g, ok);
        }
        for (int idx = tid; idx < 9 * 16 * BSEG; idx += 128) {
            int tap = idx / (16 * BSEG);
            int r = idx - tap * 16 * BSEG;
            int row = r / BSEG, seg = r - row * BSEG;
            size_t o = ((size_t)(tap * C + c0 + row)) * C + n0 + seg * 8;
            uint32_t d = sptr(bB + tap * 2 * B_ST + row * BPITCH + seg * 8);
            cpasync16(d, Bh + o, 1);
            cpasync16(d + (uint32_t)(B_ST * 2), Bl + o, 1);
        }
        asm volatile("cp.async.commit_group;" ::: "memory");
        asm volatile("cp.async.wait_group 0;" ::: "memory");
        __syncthreads();

        for (int tap = 0; tap < 9; tap++) {
            const bf16* bH = bB + tap * 2 * B_ST;
            const bf16* bL = bH + B_ST;
            const int woff = 25 * tap;
            uint32_t ah[4][4], al[4][4], bh[8][2], bl[8][2];
            #pragma unroll
            for (int mt = 0; mt < 4; mt++) {
                int row = woff + wm * 64 + mt * 16 + (lane & 15);
                int col = (lane >> 4) * 8;
                ldsm_x4(ah[mt], sptr(aH + row * APITCH + col));
                ldsm_x4(al[mt], sptr(aL + row * APITCH + col));
            }
            #pragma unroll
            for (int np = 0; np < 4; np++) {
                uint32_t t0[4], t1[4];
                int krow = lane & 15;
                int col = wn * 64 + np * 16 + (lane >> 4) * 8;
                ldsm_x4_t(t0, sptr(bH + krow * BPITCH + col));
                ldsm_x4_t(t1, sptr(bL + krow * BPITCH + col));
                bh[np * 2][0] = t0[0]; bh[np * 2][1] = t0[1];
                bh[np * 2 + 1][0] = t0[2]; bh[np * 2 + 1][1] = t0[3];
                bl[np * 2][0] = t1[0]; bl[np * 2][1] = t1[1];
                bl[np * 2 + 1][0] = t1[2]; bl[np * 2 + 1][1] = t1[3];
            }
            #pragma unroll
            for (int mt = 0; mt < 4; mt++)
                #pragma unroll
                for (int nt = 0; nt < 8; nt++) {
                    mma16816(acc[mt][nt], ah[mt], bh[nt]);
                    mma16816(acc[mt][nt], ah[mt], bl[nt]);
                    mma16816(acc[mt][nt], al[mt], bh[nt]);
                }
        }
        __syncthreads();
    }

    const int rbase = m0 + wm * 64 + (lane >> 2);
    const int cbase = n0 + wn * 64 + 2 * (lane & 3);
    #pragma unroll
    for (int mt = 0; mt < 4; mt++) {
        #pragma unroll
        for (int half = 0; half < 2; half++) {
            int row = rbase + mt * 16 + half * 8;
            if (row >= M) continue;
            #pragma unroll
            for (int nt = 0; nt < 8; nt++) {
                int col = cbase + nt * 8;
                float x = fmaxf(acc[mt][nt][half * 2 + 0], 0.f);
                float y = fmaxf(acc[mt][nt][half * 2 + 1], 0.f);
                if (MODE_OUT == 1) {
                    float2 p = make_float2(x, y);
                    *(float2*)(OutF + ((size_t)bz * M + row) * C + col) = p;
                } else {
                    int t = row / VJ, v = row - t * VJ;
                    OutF[(((size_t)bz * C + col) * Tout + t) * VJ + v] = x;
                    OutF[(((size_t)bz * C + col + 1) * Tout + t) * VJ + v] = y;
                }
            }
        }
    }
}

// ---------------- stride-2 tconv: window + row gather (PROVEN R13) ----------
__global__ void __launch_bounds__(128, 2) tconv_s2w(
    const bf16* __restrict__ Ah, const bf16* __restrict__ Al,
    const bf16* __restrict__ Bh, const bf16* __restrict__ Bl,
    float* __restrict__ OutF, int Mout, int C, int Tin) {

    constexpr int BM = 250, BN = 64;
    constexpr int WR = 675;
    constexpr int APITCH = 24;
    constexpr int A_ST = WR * APITCH;
    constexpr int BPITCH = BN + 8;
    constexpr int B_ST = 16 * BPITCH;
    constexpr int BSEG = BN / 8;
    extern __shared__ __align__(128) bf16 smem[];
    bf16* aH = smem;
    bf16* aL = smem + A_ST;
    bf16* bB = smem + 2 * A_ST;
    __shared__ int rowmap[256];

    const int tid = threadIdx.x;
    const int lane = tid & 31, wid = tid >> 5;
    const int wm = wid;
    const int m0 = blockIdx.x * BM;
    const int n0 = blockIdx.y * BN;
    const int bz = blockIdx.z;
    const int Min = Tin * VJ;
    const int t0 = m0 / VJ;
    const int f0 = 2 * m0 - 100;

    for (int r = tid; r < 256; r += 128) {
        int gm = m0 + r;
        int rmv = 0;
        if (r < BM && gm < Mout) {
            int t = gm / VJ, v = gm - t * VJ;
            rmv = 50 * (t - t0) + v;
        }
        rowmap[r] = rmv;
    }
    const bf16* An_h = Ah + (size_t)bz * Min * C;
    const bf16* An_l = Al + (size_t)bz * Min * C;
    __syncthreads();

    int rm[4];
    #pragma unroll
    for (int mt = 0; mt < 4; mt++)
        rm[mt] = rowmap[wm * 64 + mt * 16 + (lane & 15)];

    float acc[4][8][4];
    #pragma unroll
    for (int a = 0; a < 4; a++)
        #pragma unroll
        for (int b = 0; b < 8; b++)
            #pragma unroll
            for (int c = 0; c < 4; c++) acc[a][b][c] = 0.f;

    const int nch = C >> 4;
    for (int ch = 0; ch < nch; ch++) {
        const int c0 = ch << 4;
        for (int idx = tid; idx < WR * 2; idx += 128) {
            int w = idx >> 1, seg = idx & 1;
            int flat = f0 + w;
            int ok = (flat >= 0 && flat < Min);
            size_t g = ok ? ((size_t)flat * C + c0 + seg * 8) : 0;
            uint32_t d = sptr(aH + w * APITCH + seg * 8);
            cpasync16(d, An_h + g, ok);
            cpasync16(d + (uint32_t)(A_ST * 2), An_l + g, ok);
        }
        for (int idx = tid; idx < 9 * 16 * BSEG; idx += 128) {
            int tap = idx / (16 * BSEG);
            int r = idx - tap * 16 * BSEG;
            int row = r / BSEG, seg = r - row * BSEG;
            size_t o = ((size_t)(tap * C + c0 + row)) * C + n0 + seg * 8;
            uint32_t d = sptr(bB + tap * 2 * B_ST + row * BPITCH + seg * 8);
            cpasync16(d, Bh + o, 1);
            cpasync16(d + (uint32_t)(B_ST * 2), Bl + o, 1);
        }
        asm volatile("cp.async.commit_group;" ::: "memory");
        asm volatile("cp.async.wait_group 0;" ::: "memory");
        __syncthreads();

        for (int tap = 0; tap < 9; tap++) {
            const bf16* bH = bB + tap * 2 * B_ST;
            const bf16* bL = bH + B_ST;
            const int woff = 25 * tap;
            uint32_t ah[4][4], al[4][4], bh[8][2], bl[8][2];
            #pragma unroll
            for (int mt = 0; mt < 4; mt++) {
                int row = rm[mt] + woff;
                int col = (lane >> 4) * 8;
                ldsm_x4(ah[mt], sptr(aH + row * APITCH + col));
                ldsm_x4(al[mt], sptr(aL + row * APITCH + col));
            }
            #pragma unroll
            for (int np = 0; np < 4; np++) {
                uint32_t t0r[4], t1r[4];
                int krow = lane & 15;
                int col = np * 16 + (lane >> 4) * 8;
                ldsm_x4_t(t0r, sptr(bH + krow * BPITCH + col));
                ldsm_x4_t(t1r, sptr(bL + krow * BPITCH + col));
                bh[np * 2][0] = t0r[0]; bh[np * 2][1] = t0r[1];
                bh[np * 2 + 1][0] = t0r[2]; bh[np * 2 + 1][1] = t0r[3];
                bl[np * 2][0] = t1r[0]; bl[np * 2][1] = t1r[1];
                bl[np * 2 + 1][0] = t1r[2]; bl[np * 2 + 1][1] = t1r[3];
            }
            #pragma unroll
            for (int mt = 0; mt < 4; mt++)
                #pragma unroll
                for (int nt = 0; nt < 8; nt++) {
                    mma16816(acc[mt][nt], ah[mt], bh[nt]);
                    mma16816(acc[mt][nt], ah[mt], bl[nt]);
                    mma16816(acc[mt][nt], al[mt], bh[nt]);
                }
        }
        __syncthreads();
    }

    const int rbase = wm * 64 + (lane >> 2);
    const int cbase = n0 + 2 * (lane & 3);
    #pragma unroll
    for (int mt = 0; mt < 4; mt++) {
        #pragma unroll
        for (int half = 0; half < 2; half++) {
            int lr = rbase + mt * 16 + half * 8;
            int row = m0 + lr;
            if (lr >= BM || row >= Mout) continue;
            #pragma unroll
            for (int nt = 0; nt < 8; nt++) {
                int col = cbase + nt * 8;
                float x = fmaxf(acc[mt][nt][half * 2 + 0], 0.f);
                float y = fmaxf(acc[mt][nt][half * 2 + 1], 0.f);
                float2 p = make_float2(x, y);
                *(float2*)(OutF + ((size_t)bz * Mout + row) * C + col) = p;
            }
        }
    }
}

// ---------------- mix GEMM: 64x64 tiles, 3-stage cp.async pipeline (PROVEN R13) ----------
template <int BM, int BN>
__global__ void __launch_bounds__(128, 2) gemm64(
    const bf16* __restrict__ Ah, const bf16* __restrict__ Al,
    const bf16* __restrict__ Bh, const bf16* __restrict__ Bl,
    bf16* __restrict__ OutH, bf16* __restrict__ OutL,
    int M, int Ka, int N) {

    constexpr int STAGES = 3;
    constexpr int APITCH = 24;
    constexpr int A_ST = BM * APITCH;
    constexpr int BPITCH = BN + 8;
    constexpr int B_ST = 16 * BPITCH;
    constexpr int STG = 2 * A_ST + 2 * B_ST;
    constexpr int WM = BM / 64;
    constexpr int BSEG = BN / 8;
    extern __shared__ __align__(128) bf16 smem[];

    const int tid = threadIdx.x;
    const int lane = tid & 31, wid = tid >> 5;
    const int wm = wid % WM, wn = wid / WM;
    const int m0 = blockIdx.x * BM;
    const int n0 = blockIdx.y * BN;

    float acc[4][8][4];
    #pragma unroll
    for (int a = 0; a < 4; a++)
        #pragma unroll
        for (int b = 0; b < 8; b++)
            #pragma unroll
            for (int c = 0; c < 4; c++) acc[a][b][c] = 0.f;

    const int nch = Ka >> 4;

    auto load_stage = [&](int s, int ch) {
        int c0 = ch << 4;
        bf16* aH = smem + s * STG;
        bf16* bB = aH + 2 * A_ST;
        for (int idx = tid; idx < BM * 2; idx += 128) {
            int w = idx >> 1, seg = idx & 1;
            int gm = m0 + w;
            int ok = gm < M;
            size_t g = ok ? ((size_t)gm * Ka + c0 + seg * 8) : 0;
            uint32_t d = sptr(aH + w * APITCH + seg * 8);
            cpasync16(d, Ah + g, ok);
            cpasync16(d + (uint32_t)(A_ST * 2), Al + g, ok);
        }
        for (int idx = tid; idx < 16 * BSEG; idx += 128) {
            int row = idx / BSEG, seg = idx - row * BSEG;
            size_t o = ((size_t)(c0 + row)) * N + n0 + seg * 8;
            uint32_t d = sptr(bB + row * BPITCH + seg * 8);
            cpasync16(d, Bh + o, 1);
            cpasync16(d + (uint32_t)(B_ST * 2), Bl + o, 1);
        }
    };

    #pragma unroll
    for (int s = 0; s < STAGES - 1; s++) {
        if (s < nch) load_stage(s, s);
        asm volatile("cp.async.commit_group;" ::: "memory");
    }

    for (int ch = 0; ch < nch; ch++) {
        asm volatile("cp.async.wait_group %0;" :: "n"(STAGES - 2) : "memory");
        __syncthreads();
        int pf = ch + STAGES - 1;
        if (pf < nch) load_stage(pf % STAGES, pf);
        asm volatile("cp.async.commit_group;" ::: "memory");

        const int s = ch % STAGES;
        const bf16* aH = smem + s * STG;
        const bf16* aL = aH + A_ST;
        const bf16* bH = aH + 2 * A_ST;
        const bf16* bL = bH + B_ST;
        uint32_t ah[4][4], al[4][4], bh[8][2], bl[8][2];
        #pragma unroll
        for (int mt = 0; mt < 4; mt++) {
            int row = wm * 64 + mt * 16 + (lane & 15);
            int col = (lane >> 4) * 8;
            ldsm_x4(ah[mt], sptr(aH + row * APITCH + col));
            ldsm_x4(al[mt], sptr(aL + row * APITCH + col));
        }
        #pragma unroll
        for (int np = 0; np < 4; np++) {
            uint32_t t0[4], t1[4];
            int krow = lane & 15;
            int col = wn * 64 + np * 16 + (lane >> 4) * 8;
            ldsm_x4_t(t0, sptr(bH + krow * BPITCH + col));
            ldsm_x4_t(t1, sptr(bL + krow * BPITCH + col));
            bh[np * 2][0] = t0[0]; bh[np * 2][1] = t0[1];
            bh[np * 2 + 1][0] = t0[2]; bh[np * 2 + 1][1] = t0[3];
            bl[np * 2][0] = t1[0]; bl[np * 2][1] = t1[1];
            bl[np * 2 + 1][0] = t1[2]; bl[np * 2 + 1][1] = t1[3];
        }
        #pragma unroll
        for (int mt = 0; mt < 4; mt++)
            #pragma unroll
            for (int nt = 0; nt < 8; nt++) {
                mma16816(acc[mt][nt], ah[mt], bh[nt]);
                mma16816(acc[mt][nt], ah[mt], bl[nt]);
                mma16816(acc[mt][nt], al[mt], bh[nt]);
            }
    }

    const int rbase = m0 + wm * 64 + (lane >> 2);
    const int cbase = n0 + wn * 64 + 2 * (lane & 3);
    #pragma unroll
    for (int mt = 0; mt < 4; mt++) {
        #pragma unroll
        for (int half = 0; half < 2; half++) {
            int row = rbase + mt * 16 + half * 8;
            if (row >= M) continue;
            #pragma unroll
            for (int nt = 0; nt < 8; nt++) {
                int col = cbase + nt * 8;
                float x = fmaxf(acc[mt][nt][half * 2 + 0], 0.f);
                float y = fmaxf(acc[mt][nt][half * 2 + 1], 0.f);
                bf16 hx, lx, hy, ly;
                split2(x, hx, lx); split2(y, hy, ly);
                __nv_bfloat162 ph; ph.x = hx; ph.y = hy;
                __nv_bfloat162 pl2; pl2.x = lx; pl2.y = ly;
                *(__nv_bfloat162*)(OutH + (size_t)row * N + col) = ph;
                *(__nv_bfloat162*)(OutL + (size_t)row * N + col) = pl2;
            }
        }
    }
}

// ---------------- host orchestration ----------------
static inline int cdiv(int a, int b) { return (a + b - 1) / b; }

extern "C" void kernel_launch(void* const* d_in, const int* in_sizes, int n_in,
                              void* d_out, int out_size) {
    (void)out_size;
    const float* x = (const float*)d_in[0];
    const float* A = (const float*)d_in[1];

    bool interleaved = (n_in >= 4 && in_sizes[3] == 64 * 64 * 9);
    const float* ws[10];
    const float* wt[10];
    for (int i = 0; i < 10; i++) {
        if (interleaved) {
            ws[i] = (const float*)d_in[2 + 2 * i];
            wt[i] = (const float*)d_in[3 + 2 * i];
        } else {
            ws[i] = (const float*)d_in[2 + i];
            wt[i] = (const float*)d_in[12 + i];
        }
    }

    float* X;
    bf16 *Hh, *Hl, *Gh, *Gl, *WSh, *WSl, *WTh, *WTl;
    cudaGetSymbolAddress((void**)&X, g_X);
    cudaGetSymbolAddress((void**)&Hh, g_Hh);
    cudaGetSymbolAddress((void**)&Hl, g_Hl);
    cudaGetSymbolAddress((void**)&Gh, g_Gh);
    cudaGetSymbolAddress((void**)&Gl, g_Gl);
    cudaGetSymbolAddress((void**)&WSh, g_WSh);
    cudaGetSymbolAddress((void**)&WSl, g_WSl);
    cudaGetSymbolAddress((void**)&WTh, g_WTh);
    cudaGetSymbolAddress((void**)&WTl, g_WTl);

    const int Cin[10]  = {3, 64, 64, 64, 64, 128, 128, 128, 256, 256};
    const int Cout[10] = {64, 64, 64, 64, 128, 128, 128, 256, 256, 256};
    const int Tin[10]  = {300, 300, 300, 300, 300, 150, 150, 150, 75, 75};
    const int Tout[10] = {300, 300, 300, 300, 150, 150, 150, 75, 75, 75};
    const int S[10]    = {1, 1, 1, 1, 2, 1, 1, 2, 1, 1};
    const int Kp[10]   = {32, 64, 64, 64, 64, 128, 128, 128, 256, 256};

    int wsOff[10], wtOff[10];
    {
        int o = 0, o2 = 0;
        for (int i = 0; i < 10; i++) {
            wsOff[i] = o;  o  += Kp[i] * Cout[i];
            wtOff[i] = o2; o2 += 9 * Cout[i] * Cout[i];
        }
    }

    constexpr int SMEM_W64  = (2 * 456 * 24 + 18 * 16 * 72) * 2;              // 85248
    constexpr int SMEM_W128 = (2 * 328 * 24 + 18 * 16 * 136) * 2;             // 109824
    constexpr int SMEM_S2   = (2 * 675 * 24 + 18 * 16 * 72) * 2;              // 106272
    constexpr int SMEM_G256 = 3 * (2 * 256 * 24 + 2 * 16 * 72) * 2;           // 87552
    constexpr int SMEM_G128 = 3 * (2 * 128 * 24 + 2 * 16 * 136) * 2;          // 62976
    cudaFuncSetAttribute(tconv_w64<256, 64, 1>, cudaFuncAttributeMaxDynamicSharedMemorySize, SMEM_W64);
    cudaFuncSetAttribute(tconv_w64<128, 128, 1>, cudaFuncAttributeMaxDynamicSharedMemorySize, SMEM_W128);
    cudaFuncSetAttribute(tconv_w64<128, 128, 2>, cudaFuncAttributeMaxDynamicSharedMemorySize, SMEM_W128);
    cudaFuncSetAttribute(tconv_s2w, cudaFuncAttributeMaxDynamicSharedMemorySize, SMEM_S2);
    cudaFuncSetAttribute(gemm64<128, 128>, cudaFuncAttributeMaxDynamicSharedMemorySize, SMEM_G128);
    cudaFuncSetAttribute(gemm64<256, 64>, cudaFuncAttributeMaxDynamicSharedMemorySize, SMEM_G256);

    auto do_split = [&](int i) {
        int tot = Kp[i] * Cout[i] + 9 * Cout[i] * Cout[i];
        split_both<<<cdiv(tot, 256), 256>>>(ws[i], wt[i],
                                            WSh + wsOff[i], WSl + wsOff[i],
                                            WTh + wtOff[i], WTl + wtOff[i],
                                            Cout[i], Cin[i], Kp[i]);
    };
    auto do_layer = [&](int i, const float* cur) {
        const int NT = NBATCH * Tin[i];
        if (i == 0)
            adj_kernel<<<NT, 256>>>(cur, Hh, Hl, A, Cin[i], Kp[i]);
        else
            adj_kernel4<<<NT, 256>>>(cur, Hh, Hl, A, Cin[i]);

        // channel mix + ReLU -> split bf16 G
        const int M = NT * VJ;
        if (Cout[i] >= 128) {
            dim3 grid(cdiv(M, 128), Cout[i] / 128);
            gemm64<128, 128><<<grid, 128, SMEM_G128>>>(
                Hh, Hl, WSh + wsOff[i], WSl + wsOff[i], Gh, Gl, M, Kp[i], Cout[i]);
        } else {
            dim3 grid(cdiv(M, 256), 1);
            gemm64<256, 64><<<grid, 128, SMEM_G256>>>(
                Hh, Hl, WSh + wsOff[i], WSl + wsOff[i], Gh, Gl, M, Kp[i], Cout[i]);
        }

        // temporal conv + ReLU
        const int Mout = Tout[i] * VJ;
        if (S[i] == 1) {
            if (Cout[i] >= 128) {
                dim3 grid(cdiv(Mout, 128), Cout[i] / 128, NBATCH);
                if (i == 9)
                    tconv_w64<128, 128, 2><<<grid, 128, SMEM_W128>>>(
                        Gh, Gl, WTh + wtOff[i], WTl + wtOff[i], (float*)d_out,
                        Mout, Cout[i], Tout[i]);
                else
                    tconv_w64<128, 128, 1><<<grid, 128, SMEM_W128>>>(
                        Gh, Gl, WTh + wtOff[i], WTl + wtOff[i], X,
                        Mout, Cout[i], Tout[i]);
            } else {
                dim3 grid(cdiv(Mout, 256), 1, NBATCH);
                tconv_w64<256, 64, 1><<<grid, 128, SMEM_W64>>>(
                    Gh, Gl, WTh + wtOff[i], WTl + wtOff[i], X,
                    Mout, Cout[i], Tout[i]);
            }
        } else {
            dim3 grid(cdiv(Mout, 250), Cout[i] / 64, NBATCH);
            tconv_s2w<<<grid, 128, SMEM_S2>>>(
                Gh, Gl, WTh + wtOff[i], WTl + wtOff[i],
                X, Mout, Cout[i], Tin[i]);
        }
    };

    // Launch order: 0:split0  1:adj0  2:mix0  3:tconv0  (ncu captures idx 3)
    do_split(0);
    do_layer(0, x);
    for (int i = 1; i < 10; i++) do_split(i);
    for (int i = 1; i < 10; i++) do_layer(i, X);
}

// round 17
// speedup vs baseline: 1.1388x; 1.0037x over previous
#include <cuda_runtime.h>
#include <cuda_bf16.h>
#include <cstdint>

#define VJ 25
#define NBATCH 64
typedef __nv_bfloat16 bf16;

// ---------------- static device scratch ----------------
__device__ float g_X[30720000];                      // tconv fp32 outputs (n, m, C)
__device__ bf16  g_Hh[30720000], g_Hl[30720000];     // adjacency out, split bf16
__device__ bf16  g_Gh[61440000], g_Gl[61440000];     // mix out, split bf16
__device__ bf16  g_WSh[262144],  g_WSl[262144];      // split 1x1 weights [c][o]
__device__ bf16  g_WTh[2359296], g_WTl[2359296];     // split temporal weights [tap][i][o]

// ---------------- helpers ----------------
__device__ __forceinline__ uint32_t sptr(const void* p) {
    return (uint32_t)__cvta_generic_to_shared(p);
}
__device__ __forceinline__ void split2(float v, bf16& h, bf16& l) {
    h = __float2bfloat16(v);
    l = __float2bfloat16(v - __bfloat162float(h));
}
__device__ __forceinline__ float2 ffma2(float2 d, float2 a, float2 b) {
    unsigned long long ud = reinterpret_cast<unsigned long long&>(d);
    unsigned long long ua = reinterpret_cast<unsigned long long&>(a);
    unsigned long long ub = reinterpret_cast<unsigned long long&>(b);
    asm("fma.rn.f32x2 %0, %1, %2, %0;" : "+l"(ud) : "l"(ua), "l"(ub));
    return reinterpret_cast<float2&>(ud);
}
__device__ __forceinline__ void ldsm_x4(uint32_t* r, uint32_t addr) {
    asm volatile("ldmatrix.sync.aligned.m8n8.x4.shared.b16 {%0,%1,%2,%3}, [%4];"
                 : "=r"(r[0]), "=r"(r[1]), "=r"(r[2]), "=r"(r[3]) : "r"(addr));
}
__device__ __forceinline__ void ldsm_x4_t(uint32_t* r, uint32_t addr) {
    asm volatile("ldmatrix.sync.aligned.m8n8.x4.trans.shared.b16 {%0,%1,%2,%3}, [%4];"
                 : "=r"(r[0]), "=r"(r[1]), "=r"(r[2]), "=r"(r[3]) : "r"(addr));
}
__device__ __forceinline__ void mma16816(float* d, const uint32_t* a, const uint32_t* b) {
    asm volatile(
        "mma.sync.aligned.m16n8k16.row.col.f32.bf16.bf16.f32 "
        "{%0,%1,%2,%3}, {%4,%5,%6,%7}, {%8,%9}, {%0,%1,%2,%3};"
        : "+f"(d[0]), "+f"(d[1]), "+f"(d[2]), "+f"(d[3])
        : "r"(a[0]), "r"(a[1]), "r"(a[2]), "r"(a[3]), "r"(b[0]), "r"(b[1]));
}
__device__ __forceinline__ void cpasync16(uint32_t d, const void* g, int ok) {
    asm volatile("cp.async.cg.shared.global [%0], [%1], 16, %2;"
                 :: "r"(d), "l"(g), "r"(ok ? 16 : 0) : "memory");
}

// ---------------- fused weight split ----------------
__global__ void split_both(const float* __restrict__ ws, const float* __restrict__ wt,
                           bf16* __restrict__ wsh, bf16* __restrict__ wsl,
                           bf16* __restrict__ wth, bf16* __restrict__ wtl,
                           int Cout, int Cin, int Kp) {
    int idx = blockIdx.x * 256 + threadIdx.x;
    int nws = Kp * Cout;
    if (idx < nws) {
        int c = idx / Cout, o = idx - c * Cout;
        float v = (c < Cin) ? ws[o * Cin + c] : 0.f;
        bf16 hh, ll; split2(v, hh, ll);
        wsh[idx] = hh; wsl[idx] = ll;
        return;
    }
    int j = idx - nws;
    if (j < 9 * Cout * Cout) {
        int k = j / (Cout * Cout);
        int r = j - k * Cout * Cout;
        int i = r / Cout, o = r - i * Cout;
        float v = wt[((size_t)o * Cout + i) * 9 + k];
        bf16 hh, ll; split2(v, hh, ll);
        wth[j] = hh; wtl[j] = ll;   // [(tap*C + i)*C + o]
    }
}

// ---------------- adjacency, scalar (layer 0) ----------------
__global__ void adj_kernel(const float* __restrict__ in, bf16* __restrict__ Hh,
                           bf16* __restrict__ Hl, const float* __restrict__ A,
                           int C, int Kp) {
    __shared__ float sA[VJ * VJ];
    __shared__ float sF[VJ * 256];
    const size_t bin = (size_t)blockIdx.x * VJ * C;
    const size_t bout = (size_t)blockIdx.x * VJ * Kp;
    for (int i = threadIdx.x; i < VJ * VJ; i += 256) sA[i] = A[i];
    const int tot = VJ * C;
    for (int i = threadIdx.x; i < tot; i += 256) sF[i] = in[bin + i];
    __syncthreads();
    const int outn = VJ * Kp;
    for (int i = threadIdx.x; i < outn; i += 256) {
        int w = i / Kp, c = i - w * Kp;
        float acc = 0.f;
        if (c < C) {
            #pragma unroll
            for (int v = 0; v < VJ; v++) acc = fmaf(sA[v * VJ + w], sF[v * C + c], acc);
        }
        bf16 hh, ll; split2(acc, hh, ll);
        Hh[bout + i] = hh; Hl[bout + i] = ll;
    }
}

// ---------------- adjacency, float4 + packed ffma2 (layers 1-9) ----------------
__global__ void adj_kernel4(const float* __restrict__ in, bf16* __restrict__ Hh,
                            bf16* __restrict__ Hl, const float* __restrict__ A,
                            int C) {
    __shared__ float sA[VJ * VJ];
    __shared__ __align__(16) float sF[VJ * 256];
    const size_t base = (size_t)blockIdx.x * VJ * C;
    for (int i = threadIdx.x; i < VJ * VJ; i += 256) sA[i] = A[i];
    const int tot4 = VJ * C / 4;
    const float4* in4 = (const float4*)(in + base);
    float4* sF4 = (float4*)sF;
    for (int i = threadIdx.x; i < tot4; i += 256) sF4[i] = in4[i];
    __syncthreads();
    const int C4 = C >> 2;
    for (int i = threadIdx.x; i < VJ * C4; i += 256) {
        int w = i / C4, c4 = i - w * C4;
        float2 a0 = make_float2(0.f, 0.f), a1 = make_float2(0.f, 0.f);
        #pragma unroll
        for (int v = 0; v < VJ; v++) {
            float a = sA[v * VJ + w];
            float4 f = sF4[v * C4 + c4];
            float2 aa = make_float2(a, a);
            a0 = ffma2(a0, aa, make_float2(f.x, f.y));
            a1 = ffma2(a1, aa, make_float2(f.z, f.w));
        }
        bf16 h0, l0, h1, l1, h2, l2, h3, l3;
        split2(a0.x, h0, l0); split2(a0.y, h1, l1);
        split2(a1.x, h2, l2); split2(a1.y, h3, l3);
        size_t o = base + (size_t)w * C + c4 * 4;
        __nv_bfloat162 ph0; ph0.x = h0; ph0.y = h1;
        __nv_bfloat162 ph1; ph1.x = h2; ph1.y = h3;
        __nv_bfloat162 pl0; pl0.x = l0; pl0.y = l1;
        __nv_bfloat162 pl1; pl1.x = l2; pl1.y = l3;
        *(__nv_bfloat162*)(Hh + o) = ph0;
        *(__nv_bfloat162*)(Hh + o + 2) = ph1;
        *(__nv_bfloat162*)(Hl + o) = pl0;
        *(__nv_bfloat162*)(Hl + o + 2) = pl1;
    }
}

// ---------------- stride-1 tconv: 64x64 warp tiles + chunk dephasing ----------
template <int BM, int BN, int MODE_OUT>
__global__ void __launch_bounds__(128, 2) tconv_w64(
    const bf16* __restrict__ Ah, const bf16* __restrict__ Al,
    const bf16* __restrict__ Bh, const bf16* __restrict__ Bl,
    float* __restrict__ OutF, int M, int C, int Tout) {

    constexpr int WR = BM + 200;
    constexpr int APITCH = 24;
    constexpr int A_ST = WR * APITCH;
    constexpr int BPITCH = BN + 8;
    constexpr int B_ST = 16 * BPITCH;
    constexpr int WM = BM / 64;
    constexpr int BSEG = BN / 8;
    extern __shared__ __align__(128) bf16 smem[];
    bf16* aH = smem;
    bf16* aL = smem + A_ST;
    bf16* bB = smem + 2 * A_ST;

    const int tid = threadIdx.x;
    const int lane = tid & 31, wid = tid >> 5;
    const int wm = wid % WM, wn = wid / WM;
    const int m0 = blockIdx.x * BM;
    const int n0 = blockIdx.y * BN;
    const int bz = blockIdx.z;

    const bf16* An_h = Ah + (size_t)bz * M * C;
    const bf16* An_l = Al + (size_t)bz * M * C;

    float acc[4][8][4];
    #pragma unroll
    for (int a = 0; a < 4; a++)
        #pragma unroll
        for (int b = 0; b < 8; b++)
            #pragma unroll
            for (int c = 0; c < 4; c++) acc[a][b][c] = 0.f;

    const int nch = C >> 4;
    // Dephase co-resident CTAs: wave-1 pairs are ~148 bids apart -> opposite half-phase.
    const int linb = blockIdx.x + gridDim.x * (blockIdx.y + gridDim.y * blockIdx.z);
    const int st = ((linb / 148) & 1) * (nch >> 1);
    for (int ci = 0; ci < nch; ci++) {
        int ch = ci + st; if (ch >= nch) ch -= nch;
        const int c0 = ch << 4;
        for (int idx = tid; idx < WR * 2; idx += 128) {
            int w = idx >> 1, seg = idx & 1;
            int flat = m0 - 100 + w;
            int ok = (flat >= 0 && flat < M);
            size_t g = ok ? ((size_t)flat * C + c0 + seg * 8) : 0;
            uint32_t d = sptr(aH + w * APITCH + seg * 8);
            cpasync16(d, An_h + g, ok);
            cpasync16(d + (uint32_t)(A_ST * 2), An_l + g, ok);
        }
        for (int idx = tid; idx < 9 * 16 * BSEG; idx += 128) {
            int tap = idx / (16 * BSEG);
            int r = idx - tap * 16 * BSEG;
            int row = r / BSEG, seg = r - row * BSEG;
            size_t o = ((size_t)(tap * C + c0 + row)) * C + n0 + seg * 8;
            uint32_t d = sptr(bB + tap * 2 * B_ST + row * BPITCH + seg * 8);
            cpasync16(d, Bh + o, 1);
            cpasync16(d + (uint32_t)(B_ST * 2), Bl + o, 1);
        }
        asm volatile("cp.async.commit_group;" ::: "memory");
        asm volatile("cp.async.wait_group 0;" ::: "memory");
        __syncthreads();

        for (int tap = 0; tap < 9; tap++) {
            const bf16* bH = bB + tap * 2 * B_ST;
            const bf16* bL = bH + B_ST;
            const int woff = 25 * tap;
            uint32_t ah[4][4], al[4][4], bh[8][2], bl[8][2];
            #pragma unroll
            for (int mt = 0; mt < 4; mt++) {
                int row = woff + wm * 64 + mt * 16 + (lane & 15);
                int col = (lane >> 4) * 8;
                ldsm_x4(ah[mt], sptr(aH + row * APITCH + col));
                ldsm_x4(al[mt], sptr(aL + row * APITCH + col));
            }
            #pragma unroll
            for (int np = 0; np < 4; np++) {
                uint32_t t0[4], t1[4];
                int krow = lane & 15;
                int col = wn * 64 + np * 16 + (lane >> 4) * 8;
                ldsm_x4_t(t0, sptr(bH + krow * BPITCH + col));
                ldsm_x4_t(t1, sptr(bL + krow * BPITCH + col));
                bh[np * 2][0] = t0[0]; bh[np * 2][1] = t0[1];
                bh[np * 2 + 1][0] = t0[2]; bh[np * 2 + 1][1] = t0[3];
                bl[np * 2][0] = t1[0]; bl[np * 2][1] = t1[1];
                bl[np * 2 + 1][0] = t1[2]; bl[np * 2 + 1][1] = t1[3];
            }
            #pragma unroll
            for (int mt = 0; mt < 4; mt++)
                #pragma unroll
                for (int nt = 0; nt < 8; nt++) {
                    mma16816(acc[mt][nt], ah[mt], bh[nt]);
                    mma16816(acc[mt][nt], ah[mt], bl[nt]);
                    mma16816(acc[mt][nt], al[mt], bh[nt]);
                }
        }
        __syncthreads();
    }

    const int rbase = m0 + wm * 64 + (lane >> 2);
    const int cbase = n0 + wn * 64 + 2 * (lane & 3);
    #pragma unroll
    for (int mt = 0; mt < 4; mt++) {
        #pragma unroll
        for (int half = 0; half < 2; half++) {
            int row = rbase + mt * 16 + half * 8;
            if (row >= M) continue;
            #pragma unroll
            for (int nt = 0; nt < 8; nt++) {
                int col = cbase + nt * 8;
                float x = fmaxf(acc[mt][nt][half * 2 + 0], 0.f);
                float y = fmaxf(acc[mt][nt][half * 2 + 1], 0.f);
                if (MODE_OUT == 1) {
                    float2 p = make_float2(x, y);
                    *(float2*)(OutF + ((size_t)bz * M + row) * C + col) = p;
                } else {
                    int t = row / VJ, v = row - t * VJ;
                    OutF[(((size_t)bz * C + col) * Tout + t) * VJ + v] = x;
                    OutF[(((size_t)bz * C + col + 1) * Tout + t) * VJ + v] = y;
                }
            }
        }
    }
}

// ---------------- stride-2 tconv: window + row gather + chunk dephasing ----------
__global__ void __launch_bounds__(128, 2) tconv_s2w(
    const bf16* __restrict__ Ah, const bf16* __restrict__ Al,
    const bf16* __restrict__ Bh, const bf16* __restrict__ Bl,
    float* __restrict__ OutF, int Mout, int C, int Tin) {

    constexpr int BM = 250, BN = 64;
    constexpr int WR = 675;
    constexpr int APITCH = 24;
    constexpr int A_ST = WR * APITCH;
    constexpr int BPITCH = BN + 8;
    constexpr int B_ST = 16 * BPITCH;
    constexpr int BSEG = BN / 8;
    extern __shared__ __align__(128) bf16 smem[];
    bf16* aH = smem;
    bf16* aL = smem + A_ST;
    bf16* bB = smem + 2 * A_ST;
    __shared__ int rowmap[256];

    const int tid = threadIdx.x;
    const int lane = tid & 31, wid = tid >> 5;
    const int wm = wid;
    const int m0 = blockIdx.x * BM;
    const int n0 = blockIdx.y * BN;
    const int bz = blockIdx.z;
    const int Min = Tin * VJ;
    const int t0 = m0 / VJ;
    const int f0 = 2 * m0 - 100;

    for (int r = tid; r < 256; r += 128) {
        int gm = m0 + r;
        int rmv = 0;
        if (r < BM && gm < Mout) {
            int t = gm / VJ, v = gm - t * VJ;
            rmv = 50 * (t - t0) + v;
        }
        rowmap[r] = rmv;
    }
    const bf16* An_h = Ah + (size_t)bz * Min * C;
    const bf16* An_l = Al + (size_t)bz * Min * C;
    __syncthreads();

    int rm[4];
    #pragma unroll
    for (int mt = 0; mt < 4; mt++)
        rm[mt] = rowmap[wm * 64 + mt * 16 + (lane & 15)];

    float acc[4][8][4];
    #pragma unroll
    for (int a = 0; a < 4; a++)
        #pragma unroll
        for (int b = 0; b < 8; b++)
            #pragma unroll
            for (int c = 0; c < 4; c++) acc[a][b][c] = 0.f;

    const int nch = C >> 4;
    const int linb = blockIdx.x + gridDim.x * (blockIdx.y + gridDim.y * blockIdx.z);
    const int st = ((linb / 148) & 1) * (nch >> 1);
    for (int ci = 0; ci < nch; ci++) {
        int ch = ci + st; if (ch >= nch) ch -= nch;
        const int c0 = ch << 4;
        for (int idx = tid; idx < WR * 2; idx += 128) {
            int w = idx >> 1, seg = idx & 1;
            int flat = f0 + w;
            int ok = (flat >= 0 && flat < Min);
            size_t g = ok ? ((size_t)flat * C + c0 + seg * 8) : 0;
            uint32_t d = sptr(aH + w * APITCH + seg * 8);
            cpasync16(d, An_h + g, ok);
            cpasync16(d + (uint32_t)(A_ST * 2), An_l + g, ok);
        }
        for (int idx = tid; idx < 9 * 16 * BSEG; idx += 128) {
            int tap = idx / (16 * BSEG);
            int r = idx - tap * 16 * BSEG;
            int row = r / BSEG, seg = r - row * BSEG;
            size_t o = ((size_t)(tap * C + c0 + row)) * C + n0 + seg * 8;
            uint32_t d = sptr(bB + tap * 2 * B_ST + row * BPITCH + seg * 8);
            cpasync16(d, Bh + o, 1);
            cpasync16(d + (uint32_t)(B_ST * 2), Bl + o, 1);
        }
        asm volatile("cp.async.commit_group;" ::: "memory");
        asm volatile("cp.async.wait_group 0;" ::: "memory");
        __syncthreads();

        for (int tap = 0; tap < 9; tap++) {
            const bf16* bH = bB + tap * 2 * B_ST;
            const bf16* bL = bH + B_ST;
            const int woff = 25 * tap;
            uint32_t ah[4][4], al[4][4], bh[8][2], bl[8][2];
            #pragma unroll
            for (int mt = 0; mt < 4; mt++) {
                int row = rm[mt] + woff;
                int col = (lane >> 4) * 8;
                ldsm_x4(ah[mt], sptr(aH + row * APITCH + col));
                ldsm_x4(al[mt], sptr(aL + row * APITCH + col));
            }
            #pragma unroll
            for (int np = 0; np < 4; np++) {
                uint32_t t0r[4], t1r[4];
                int krow = lane & 15;
                int col = np * 16 + (lane >> 4) * 8;
                ldsm_x4_t(t0r, sptr(bH + krow * BPITCH + col));
                ldsm_x4_t(t1r, sptr(bL + krow * BPITCH + col));
                bh[np * 2][0] = t0r[0]; bh[np * 2][1] = t0r[1];
                bh[np * 2 + 1][0] = t0r[2]; bh[np * 2 + 1][1] = t0r[3];
                bl[np * 2][0] = t1r[0]; bl[np * 2][1] = t1r[1];
                bl[np * 2 + 1][0] = t1r[2]; bl[np * 2 + 1][1] = t1r[3];
            }
            #pragma unroll
            for (int mt = 0; mt < 4; mt++)
                #pragma unroll
                for (int nt = 0; nt < 8; nt++) {
                    mma16816(acc[mt][nt], ah[mt], bh[nt]);
                    mma16816(acc[mt][nt], ah[mt], bl[nt]);
                    mma16816(acc[mt][nt], al[mt], bh[nt]);
                }
        }
        __syncthreads();
    }

    const int rbase = wm * 64 + (lane >> 2);
    const int cbase = n0 + 2 * (lane & 3);
    #pragma unroll
    for (int mt = 0; mt < 4; mt++) {
        #pragma unroll
        for (int half = 0; half < 2; half++) {
            int lr = rbase + mt * 16 + half * 8;
            int row = m0 + lr;
            if (lr >= BM || row >= Mout) continue;
            #pragma unroll
            for (int nt = 0; nt < 8; nt++) {
                int col = cbase + nt * 8;
                float x = fmaxf(acc[mt][nt][half * 2 + 0], 0.f);
                float y = fmaxf(acc[mt][nt][half * 2 + 1], 0.f);
                float2 p = make_float2(x, y);
                *(float2*)(OutF + ((size_t)bz * Mout + row) * C + col) = p;
            }
        }
    }
}

// ---------------- mix GEMM: 64x64 tiles, 3-stage cp.async pipeline (PROVEN) ----------
template <int BM, int BN>
__global__ void __launch_bounds__(128, 2) gemm64(
    const bf16* __restrict__ Ah, const bf16* __restrict__ Al,
    const bf16* __restrict__ Bh, const bf16* __restrict__ Bl,
    bf16* __restrict__ OutH, bf16* __restrict__ OutL,
    int M, int Ka, int N) {

    constexpr int STAGES = 3;
    constexpr int APITCH = 24;
    constexpr int A_ST = BM * APITCH;
    constexpr int BPITCH = BN + 8;
    constexpr int B_ST = 16 * BPITCH;
    constexpr int STG = 2 * A_ST + 2 * B_ST;
    constexpr int WM = BM / 64;
    constexpr int BSEG = BN / 8;
    extern __shared__ __align__(128) bf16 smem[];

    const int tid = threadIdx.x;
    const int lane = tid & 31, wid = tid >> 5;
    const int wm = wid % WM, wn = wid / WM;
    const int m0 = blockIdx.x * BM;
    const int n0 = blockIdx.y * BN;

    float acc[4][8][4];
    #pragma unroll
    for (int a = 0; a < 4; a++)
        #pragma unroll
        for (int b = 0; b < 8; b++)
            #pragma unroll
            for (int c = 0; c < 4; c++) acc[a][b][c] = 0.f;

    const int nch = Ka >> 4;

    auto load_stage = [&](int s, int ch) {
        int c0 = ch << 4;
        bf16* aH = smem + s * STG;
        bf16* bB = aH + 2 * A_ST;
        for (int idx = tid; idx < BM * 2; idx += 128) {
            int w = idx >> 1, seg = idx & 1;
            int gm = m0 + w;
            int ok = gm < M;
            size_t g = ok ? ((size_t)gm * Ka + c0 + seg * 8) : 0;
            uint32_t d = sptr(aH + w * APITCH + seg * 8);
            cpasync16(d, Ah + g, ok);
            cpasync16(d + (uint32_t)(A_ST * 2), Al + g, ok);
        }
        for (int idx = tid; idx < 16 * BSEG; idx += 128) {
            int row = idx / BSEG, seg = idx - row * BSEG;
            size_t o = ((size_t)(c0 + row)) * N + n0 + seg * 8;
            uint32_t d = sptr(bB + row * BPITCH + seg * 8);
            cpasync16(d, Bh + o, 1);
            cpasync16(d + (uint32_t)(B_ST * 2), Bl + o, 1);
        }
    };

    #pragma unroll
    for (int s = 0; s < STAGES - 1; s++) {
        if (s < nch) load_stage(s, s);
        asm volatile("cp.async.commit_group;" ::: "memory");
    }

    for (int ch = 0; ch < nch; ch++) {
        asm volatile("cp.async.wait_group %0;" :: "n"(STAGES - 2) : "memory");
        __syncthreads();
        int pf = ch + STAGES - 1;
        if (pf < nch) load_stage(pf % STAGES, pf);
        asm volatile("cp.async.commit_group;" ::: "memory");

        const int s = ch % STAGES;
        const bf16* aH = smem + s * STG;
        const bf16* aL = aH + A_ST;
        const bf16* bH = aH + 2 * A_ST;
        const bf16* bL = bH + B_ST;
        uint32_t ah[4][4], al[4][4], bh[8][2], bl[8][2];
        #pragma unroll
        for (int mt = 0; mt < 4; mt++) {
            int row = wm * 64 + mt * 16 + (lane & 15);
            int col = (lane >> 4) * 8;
            ldsm_x4(ah[mt], sptr(aH + row * APITCH + col));
            ldsm_x4(al[mt], sptr(aL + row * APITCH + col));
        }
        #pragma unroll
        for (int np = 0; np < 4; np++) {
            uint32_t t0[4], t1[4];
            int krow = lane & 15;
            int col = wn * 64 + np * 16 + (lane >> 4) * 8;
            ldsm_x4_t(t0, sptr(bH + krow * BPITCH + col));
            ldsm_x4_t(t1, sptr(bL + krow * BPITCH + col));
            bh[np * 2][0] = t0[0]; bh[np * 2][1] = t0[1];
            bh[np * 2 + 1][0] = t0[2]; bh[np * 2 + 1][1] = t0[3];
            bl[np * 2][0] = t1[0]; bl[np * 2][1] = t1[1];
            bl[np * 2 + 1][0] = t1[2]; bl[np * 2 + 1][1] = t1[3];
        }
        #pragma unroll
        for (int mt = 0; mt < 4; mt++)
            #pragma unroll
            for (int nt = 0; nt < 8; nt++) {
                mma16816(acc[mt][nt], ah[mt], bh[nt]);
                mma16816(acc[mt][nt], ah[mt], bl[nt]);
                mma16816(acc[mt][nt], al[mt], bh[nt]);
            }
    }

    const int rbase = m0 + wm * 64 + (lane >> 2);
    const int cbase = n0 + wn * 64 + 2 * (lane & 3);
    #pragma unroll
    for (int mt = 0; mt < 4; mt++) {
        #pragma unroll
        for (int half = 0; half < 2; half++) {
            int row = rbase + mt * 16 + half * 8;
            if (row >= M) continue;
            #pragma unroll
            for (int nt = 0; nt < 8; nt++) {
                int col = cbase + nt * 8;
                float x = fmaxf(acc[mt][nt][half * 2 + 0], 0.f);
                float y = fmaxf(acc[mt][nt][half * 2 + 1], 0.f);
                bf16 hx, lx, hy, ly;
                split2(x, hx, lx); split2(y, hy, ly);
                __nv_bfloat162 ph; ph.x = hx; ph.y = hy;
                __nv_bfloat162 pl2; pl2.x = lx; pl2.y = ly;
                *(__nv_bfloat162*)(OutH + (size_t)row * N + col) = ph;
                *(__nv_bfloat162*)(OutL + (size_t)row * N + col) = pl2;
            }
        }
    }
}

// ---------------- host orchestration ----------------
static inline int cdiv(int a, int b) { return (a + b - 1) / b; }

extern "C" void kernel_launch(void* const* d_in, const int* in_sizes, int n_in,
                              void* d_out, int out_size) {
    (void)out_size;
    const float* x = (const float*)d_in[0];
    const float* A = (const float*)d_in[1];

    bool interleaved = (n_in >= 4 && in_sizes[3] == 64 * 64 * 9);
    const float* ws[10];
    const float* wt[10];
    for (int i = 0; i < 10; i++) {
        if (interleaved) {
            ws[i] = (const float*)d_in[2 + 2 * i];
            wt[i] = (const float*)d_in[3 + 2 * i];
        } else {
            ws[i] = (const float*)d_in[2 + i];
            wt[i] = (const float*)d_in[12 + i];
        }
    }

    float* X;
    bf16 *Hh, *Hl, *Gh, *Gl, *WSh, *WSl, *WTh, *WTl;
    cudaGetSymbolAddress((void**)&X, g_X);
    cudaGetSymbolAddress((void**)&Hh, g_Hh);
    cudaGetSymbolAddress((void**)&Hl, g_Hl);
    cudaGetSymbolAddress((void**)&Gh, g_Gh);
    cudaGetSymbolAddress((void**)&Gl, g_Gl);
    cudaGetSymbolAddress((void**)&WSh, g_WSh);
    cudaGetSymbolAddress((void**)&WSl, g_WSl);
    cudaGetSymbolAddress((void**)&WTh, g_WTh);
    cudaGetSymbolAddress((void**)&WTl, g_WTl);

    const int Cin[10]  = {3, 64, 64, 64, 64, 128, 128, 128, 256, 256};
    const int Cout[10] = {64, 64, 64, 64, 128, 128, 128, 256, 256, 256};
    const int Tin[10]  = {300, 300, 300, 300, 300, 150, 150, 150, 75, 75};
    const int Tout[10] = {300, 300, 300, 300, 150, 150, 150, 75, 75, 75};
    const int S[10]    = {1, 1, 1, 1, 2, 1, 1, 2, 1, 1};
    const int Kp[10]   = {32, 64, 64, 64, 64, 128, 128, 128, 256, 256};

    int wsOff[10], wtOff[10];
    {
        int o = 0, o2 = 0;
        for (int i = 0; i < 10; i++) {
            wsOff[i] = o;  o  += Kp[i] * Cout[i];
            wtOff[i] = o2; o2 += 9 * Cout[i] * Cout[i];
        }
    }

    constexpr int SMEM_W64  = (2 * 456 * 24 + 18 * 16 * 72) * 2;              // 85248
    constexpr int SMEM_W128 = (2 * 328 * 24 + 18 * 16 * 136) * 2;             // 109824
    constexpr int SMEM_S2   = (2 * 675 * 24 + 18 * 16 * 72) * 2;              // 106272
    constexpr int SMEM_G256 = 3 * (2 * 256 * 24 + 2 * 16 * 72) * 2;           // 87552
    constexpr int SMEM_G128 = 3 * (2 * 128 * 24 + 2 * 16 * 136) * 2;          // 62976
    cudaFuncSetAttribute(tconv_w64<256, 64, 1>, cudaFuncAttributeMaxDynamicSharedMemorySize, SMEM_W64);
    cudaFuncSetAttribute(tconv_w64<128, 128, 1>, cudaFuncAttributeMaxDynamicSharedMemorySize, SMEM_W128);
    cudaFuncSetAttribute(tconv_w64<128, 128, 2>, cudaFuncAttributeMaxDynamicSharedMemorySize, SMEM_W128);
    cudaFuncSetAttribute(tconv_s2w, cudaFuncAttributeMaxDynamicSharedMemorySize, SMEM_S2);
    cudaFuncSetAttribute(gemm64<128, 128>, cudaFuncAttributeMaxDynamicSharedMemorySize, SMEM_G128);
    cudaFuncSetAttribute(gemm64<256, 64>, cudaFuncAttributeMaxDynamicSharedMemorySize, SMEM_G256);

    auto do_split = [&](int i) {
        int tot = Kp[i] * Cout[i] + 9 * Cout[i] * Cout[i];
        split_both<<<cdiv(tot, 256), 256>>>(ws[i], wt[i],
                                            WSh + wsOff[i], WSl + wsOff[i],
                                            WTh + wtOff[i], WTl + wtOff[i],
                                            Cout[i], Cin[i], Kp[i]);
    };
    auto do_layer = [&](int i, const float* cur) {
        const int NT = NBATCH * Tin[i];
        if (i == 0)
            adj_kernel<<<NT, 256>>>(cur, Hh, Hl, A, Cin[i], Kp[i]);
        else
            adj_kernel4<<<NT, 256>>>(cur, Hh, Hl, A, Cin[i]);

        const int M = NT * VJ;
        if (Cout[i] >= 128) {
            dim3 grid(cdiv(M, 128), Cout[i] / 128);
            gemm64<128, 128><<<grid, 128, SMEM_G128>>>(
                Hh, Hl, WSh + wsOff[i], WSl + wsOff[i], Gh, Gl, M, Kp[i], Cout[i]);
        } else {
            dim3 grid(cdiv(M, 256), 1);
            gemm64<256, 64><<<grid, 128, SMEM_G256>>>(
                Hh, Hl, WSh + wsOff[i], WSl + wsOff[i], Gh, Gl, M, Kp[i], Cout[i]);
        }

        const int Mout = Tout[i] * VJ;
        if (S[i] == 1) {
            if (Cout[i] >= 128) {
                dim3 grid(cdiv(Mout, 128), Cout[i] / 128, NBATCH);
                if (i == 9)
                    tconv_w64<128, 128, 2><<<grid, 128, SMEM_W128>>>(
                        Gh, Gl, WTh + wtOff[i], WTl + wtOff[i], (float*)d_out,
                        Mout, Cout[i], Tout[i]);
                else
                    tconv_w64<128, 128, 1><<<grid, 128, SMEM_W128>>>(
                        Gh, Gl, WTh + wtOff[i], WTl + wtOff[i], X,
                        Mout, Cout[i], Tout[i]);
            } else {
                dim3 grid(cdiv(Mout, 256), 1, NBATCH);
                tconv_w64<256, 64, 1><<<grid, 128, SMEM_W64>>>(
                    Gh, Gl, WTh + wtOff[i], WTl + wtOff[i], X,
                    Mout, Cout[i], Tout[i]);
            }
        } else {
            dim3 grid(cdiv(Mout, 250), Cout[i] / 64, NBATCH);
            tconv_s2w<<<grid, 128, SMEM_S2>>>(
                Gh, Gl, WTh + wtOff[i], WTl + wtOff[i],
                X, Mout, Cout[i], Tin[i]);
        }
    };

    // Launch order: 0:split0  1:adj0  2:mix0  3:tconv0  (ncu captures idx 3)
    do_split(0);
    do_layer(0, x);
    for (int i = 1; i < 10; i++) do_split(i);
    for (int i = 1; i < 10; i++) do_layer(i, X);
}